// round 2
// baseline (speedup 1.0000x reference)
#include <cuda_runtime.h>
#include <math.h>

#define D_DIM 2048
#define EMB   256
#define E_EXP 64
#define MAX_N 65536

// Scratch (device-global arrays: allocation-free per harness rules)
__device__ float g_proj[(size_t)MAX_N * EMB];   // [N, 256] projection
__device__ float g_embn[EMB * E_EXP];           // normalized expert_emb [256, 64]

// ---------------------------------------------------------------------------
// Kernel 0: column-wise L2 normalization of expert_emb [EMB, E] over EMB axis
// One block per expert column e; 256 threads = one per k.
// ---------------------------------------------------------------------------
__global__ void embn_kernel(const float* __restrict__ emb) {
    __shared__ float red[EMB];
    int e = blockIdx.x;
    int t = threadIdx.x;
    float v = emb[(size_t)t * E_EXP + e];
    red[t] = v * v;
    __syncthreads();
    #pragma unroll
    for (int s = 128; s > 0; s >>= 1) {
        if (t < s) red[t] += red[t + s];
        __syncthreads();
    }
    float inv = 1.0f / sqrtf(red[0] + 1e-12f);
    g_embn[(size_t)t * E_EXP + e] = v * inv;
}

// ---------------------------------------------------------------------------
// Kernel 1: fp32 SGEMM  proj[M,256] = x[M,2048] @ W[2048,256]
// 128x128 CTA tile, BK=8, double-buffered SMEM, 4x4x(2x2) per-thread tile.
// ---------------------------------------------------------------------------
__global__ void __launch_bounds__(256, 2) sgemm_kernel(
        const float* __restrict__ A, const float* __restrict__ B, int M) {
    const int K = D_DIM;
    const int N = EMB;
    __shared__ float As[2][8][128];
    __shared__ float Bs[2][8][128];

    int bm = blockIdx.x * 128;
    int bn = blockIdx.y * 128;
    int tid = threadIdx.x;

    // A loader: 128 rows x 8 cols, one float4 per thread
    int arow = tid >> 1;
    int acol = (tid & 1) << 2;
    // B loader: 8 rows x 128 cols, one float4 per thread
    int brow = tid >> 5;
    int bcol = (tid & 31) << 2;

    const float* Ap = A + (size_t)(bm + arow) * K + acol;
    const float* Bp = B + (size_t)brow * N + bn + bcol;

    float4 a4 = *(const float4*)Ap;
    float4 b4 = *(const float4*)Bp;
    As[0][acol + 0][arow] = a4.x;
    As[0][acol + 1][arow] = a4.y;
    As[0][acol + 2][arow] = a4.z;
    As[0][acol + 3][arow] = a4.w;
    *(float4*)&Bs[0][brow][bcol] = b4;
    __syncthreads();

    int tx = tid & 15;
    int ty = tid >> 4;

    float acc[2][2][4][4];
    #pragma unroll
    for (int im = 0; im < 2; im++)
        #pragma unroll
        for (int in = 0; in < 2; in++)
            #pragma unroll
            for (int i = 0; i < 4; i++)
                #pragma unroll
                for (int j = 0; j < 4; j++)
                    acc[im][in][i][j] = 0.0f;

    const int NIT = K / 8;
    for (int kt = 0; kt < NIT; kt++) {
        int cur = kt & 1;
        int nxt = cur ^ 1;
        if (kt + 1 < NIT) {
            a4 = *(const float4*)(Ap + (kt + 1) * 8);
            b4 = *(const float4*)(Bp + (size_t)(kt + 1) * 8 * N);
        }
        #pragma unroll
        for (int k = 0; k < 8; k++) {
            float4 fa0 = *(const float4*)&As[cur][k][ty * 4];
            float4 fa1 = *(const float4*)&As[cur][k][64 + ty * 4];
            float4 fb0 = *(const float4*)&Bs[cur][k][tx * 4];
            float4 fb1 = *(const float4*)&Bs[cur][k][64 + tx * 4];
            float av[2][4] = {{fa0.x, fa0.y, fa0.z, fa0.w},
                              {fa1.x, fa1.y, fa1.z, fa1.w}};
            float bv[2][4] = {{fb0.x, fb0.y, fb0.z, fb0.w},
                              {fb1.x, fb1.y, fb1.z, fb1.w}};
            #pragma unroll
            for (int im = 0; im < 2; im++)
                #pragma unroll
                for (int in = 0; in < 2; in++)
                    #pragma unroll
                    for (int i = 0; i < 4; i++)
                        #pragma unroll
                        for (int j = 0; j < 4; j++)
                            acc[im][in][i][j] = fmaf(av[im][i], bv[in][j], acc[im][in][i][j]);
        }
        if (kt + 1 < NIT) {
            As[nxt][acol + 0][arow] = a4.x;
            As[nxt][acol + 1][arow] = a4.y;
            As[nxt][acol + 2][arow] = a4.z;
            As[nxt][acol + 3][arow] = a4.w;
            *(float4*)&Bs[nxt][brow][bcol] = b4;
        }
        __syncthreads();
    }

    // Write proj tile
    #pragma unroll
    for (int im = 0; im < 2; im++) {
        #pragma unroll
        for (int i = 0; i < 4; i++) {
            size_t row = (size_t)(bm + im * 64 + ty * 4 + i);
            #pragma unroll
            for (int in = 0; in < 2; in++) {
                float4 v = make_float4(acc[im][in][i][0], acc[im][in][i][1],
                                       acc[im][in][i][2], acc[im][in][i][3]);
                *(float4*)&g_proj[row * N + bn + in * 64 + tx * 4] = v;
            }
        }
    }
}

// ---------------------------------------------------------------------------
// Kernel 2: per-row gating epilogue.
// One warp per row: L2-normalize proj row, 64 cosine dots against SMEM emb_n
// (pair-interleaved: lane l covers experts l and l+32), top-2 (JAX tie-break:
// lowest index wins), masked softmax + raw softmax, write all 5 outputs.
// ---------------------------------------------------------------------------
__global__ void __launch_bounds__(256) gate_kernel(
        const float* __restrict__ tptr, float* __restrict__ out, int M) {
    extern __shared__ float sh[];
    float2* s_emb = (float2*)sh;                       // [256][32] pairs (e, e+32)
    int tid = threadIdx.x;
    int lane = tid & 31;
    int warp = tid >> 5;
    float* s_proj = sh + EMB * E_EXP + warp * EMB;     // 256 floats per warp

    // Fill pair-interleaved emb into SMEM
    for (int i = tid; i < EMB * 32; i += 256) {
        int k = i >> 5;
        int l = i & 31;
        s_emb[i] = make_float2(g_embn[k * 64 + l], g_embn[k * 64 + l + 32]);
    }
    __syncthreads();

    float temp = tptr[0];

    size_t nM = (size_t)M;
    float* out_ew  = out;                 // expert_weights [N,64]
    float* out_ti  = out + nM * 64;       // top_i          [N,2]
    float* out_lg  = out + nM * 66;       // logits         [N,64]
    float* out_cs  = out + nM * 130;      // cos            [N,64]
    float* out_raw = out + nM * 194;      // raw_gate_probs [N,64]

    int gw = blockIdx.x * 8 + warp;
    int nw = gridDim.x * 8;

    for (int r = gw; r < M; r += nw) {
        const float4* pr = (const float4*)(g_proj + (size_t)r * EMB);
        float4 v0 = pr[lane];
        float4 v1 = pr[lane + 32];
        float ss = v0.x * v0.x + v0.y * v0.y + v0.z * v0.z + v0.w * v0.w
                 + v1.x * v1.x + v1.y * v1.y + v1.z * v1.z + v1.w * v1.w;
        #pragma unroll
        for (int off = 16; off > 0; off >>= 1)
            ss += __shfl_xor_sync(0xffffffffu, ss, off);
        float inv = 1.0f / sqrtf(ss + 1e-12f);

        float4 n0 = make_float4(v0.x * inv, v0.y * inv, v0.z * inv, v0.w * inv);
        float4 n1 = make_float4(v1.x * inv, v1.y * inv, v1.z * inv, v1.w * inv);
        ((float4*)s_proj)[lane] = n0;
        ((float4*)s_proj)[lane + 32] = n1;
        __syncwarp();

        float c0 = 0.0f, c1 = 0.0f;
        #pragma unroll 8
        for (int k = 0; k < EMB; k++) {
            float pn = s_proj[k];
            float2 e2 = s_emb[k * 32 + lane];
            c0 = fmaf(pn, e2.x, c0);
            c1 = fmaf(pn, e2.y, c1);
        }
        __syncwarp();

        float l0 = c0 * temp;
        float l1 = c1 * temp;

        // top-1 (lowest index on ties, matching lax.top_k)
        float bv = l0; int bi = lane;
        if (l1 > bv) { bv = l1; bi = lane + 32; }
        #pragma unroll
        for (int off = 16; off > 0; off >>= 1) {
            float ov = __shfl_xor_sync(0xffffffffu, bv, off);
            int   oi = __shfl_xor_sync(0xffffffffu, bi, off);
            if (ov > bv || (ov == bv && oi < bi)) { bv = ov; bi = oi; }
        }
        float t1v = bv; int t1i = bi;

        // top-2: mask out top-1
        float m0 = (lane == t1i)      ? -INFINITY : l0;
        float m1 = (lane + 32 == t1i) ? -INFINITY : l1;
        bv = m0; bi = lane;
        if (m1 > bv || (m1 == bv && (lane + 32) < bi)) { bv = m1; bi = lane + 32; }
        #pragma unroll
        for (int off = 16; off > 0; off >>= 1) {
            float ov = __shfl_xor_sync(0xffffffffu, bv, off);
            int   oi = __shfl_xor_sync(0xffffffffu, bi, off);
            if (ov > bv || (ov == bv && oi < bi)) { bv = ov; bi = oi; }
        }
        float t2v = bv; int t2i = bi;

        // raw softmax over all 64 logits (max = t1v)
        float ex0 = expf(l0 - t1v);
        float ex1 = expf(l1 - t1v);
        float tot = ex0 + ex1;
        #pragma unroll
        for (int off = 16; off > 0; off >>= 1)
            tot += __shfl_xor_sync(0xffffffffu, tot, off);
        float r0 = ex0 / tot;
        float r1 = ex1 / tot;

        // masked softmax: only top-2 survive (exp(-1e9 - max) underflows to 0)
        float eT = expf(t2v - t1v);
        float denom = 1.0f + eT;
        float w1 = 1.0f / denom;
        float w2 = eT / denom;
        float ew0 = (lane == t1i) ? w1 : ((lane == t2i) ? w2 : 0.0f);
        float ew1 = (lane + 32 == t1i) ? w1 : ((lane + 32 == t2i) ? w2 : 0.0f);

        size_t ro = (size_t)r * 64;
        out_ew[ro + lane]       = ew0;
        out_ew[ro + lane + 32]  = ew1;
        out_lg[ro + lane]       = l0;
        out_lg[ro + lane + 32]  = l1;
        out_cs[ro + lane]       = c0;
        out_cs[ro + lane + 32]  = c1;
        out_raw[ro + lane]      = r0;
        out_raw[ro + lane + 32] = r1;
        if (lane == 0) {
            out_ti[(size_t)r * 2]     = (float)t1i;
            out_ti[(size_t)r * 2 + 1] = (float)t2i;
        }
    }
}

// ---------------------------------------------------------------------------
extern "C" void kernel_launch(void* const* d_in, const int* in_sizes, int n_in,
                              void* d_out, int out_size) {
    const float* x    = (const float*)d_in[0];   // [N, 2048]
    const float* W    = (const float*)d_in[1];   // [2048, 256]
    const float* emb  = (const float*)d_in[2];   // [256, 64]
    const float* temp = (const float*)d_in[3];   // [1]
    float* out = (float*)d_out;

    int M = in_sizes[0] / D_DIM;

    // 1) normalize expert embeddings
    embn_kernel<<<E_EXP, EMB>>>(emb);

    // 2) projection GEMM
    dim3 grid(M / 128, EMB / 128);
    sgemm_kernel<<<grid, 256>>>(x, W, M);

    // 3) fused gating epilogue
    int smem = (EMB * E_EXP + 8 * EMB) * (int)sizeof(float);  // 73728 B
    cudaFuncSetAttribute(gate_kernel, cudaFuncAttributeMaxDynamicSharedMemorySize, smem);
    gate_kernel<<<444, 256, smem>>>(temp, out, M);
}

// round 6
// speedup vs baseline: 1.1665x; 1.1665x over previous
#include <cuda_runtime.h>
#include <cuda_bf16.h>
#include <math.h>
#include <stdint.h>

#define D_DIM 2048
#define EMB   256
#define E_EXP 64
#define MAX_N 65536
#define THETA 2e-4f
#define MAXFLAG 8192

// ---------------------------------------------------------------------------
// Device-global scratch (no allocations allowed)
// ---------------------------------------------------------------------------
__device__ float g_proj[(size_t)MAX_N * EMB];     // [N, 256] projection (fp32)
__device__ float g_embn[EMB * E_EXP];             // normalized expert_emb [256,64]
__device__ int   g_nflag;
__device__ int   g_flagrows[MAXFLAG];

// bf16 split operands, plain row-major:
//   x: [M][2048]  (hi, lo)
//   W^T: [256][2048] (hi, lo)  -- K-contiguous = col-major B for mma.row.col
__device__ __align__(128) unsigned char g_xhi[(size_t)MAX_N * D_DIM * 2];
__device__ __align__(128) unsigned char g_xlo[(size_t)MAX_N * D_DIM * 2];
__device__ __align__(128) unsigned char g_whi[(size_t)EMB * D_DIM * 2];
__device__ __align__(128) unsigned char g_wlo[(size_t)EMB * D_DIM * 2];

// ---------------------------------------------------------------------------
// Base-ISA PTX helpers
// ---------------------------------------------------------------------------
__device__ __forceinline__ uint32_t smem_u32(const void* p) {
    uint32_t a;
    asm("{ .reg .u64 t; cvta.to.shared.u64 t, %1; cvt.u32.u64 %0, t; }"
        : "=r"(a) : "l"(p));
    return a;
}
__device__ __forceinline__ void cp16(uint32_t s, const void* g) {
    asm volatile("cp.async.cg.shared.global [%0], [%1], 16;"
                 :: "r"(s), "l"(g) : "memory");
}
#define CP_COMMIT() asm volatile("cp.async.commit_group;" ::: "memory")
#define CP_WAIT(n)  asm volatile("cp.async.wait_group %0;" :: "n"(n) : "memory")

#define LDSM4(R, a)                                                            \
    asm volatile("ldmatrix.sync.aligned.m8n8.x4.shared.b16 {%0,%1,%2,%3}, [%4];" \
        : "=r"((R)[0]), "=r"((R)[1]), "=r"((R)[2]), "=r"((R)[3]) : "r"(a))

#define MMA16816(C, A, B0, B1)                                                 \
    asm volatile(                                                              \
        "mma.sync.aligned.m16n8k16.row.col.f32.bf16.bf16.f32 "                 \
        "{%0,%1,%2,%3}, {%4,%5,%6,%7}, {%8,%9}, {%0,%1,%2,%3};"                \
        : "+f"((C)[0]), "+f"((C)[1]), "+f"((C)[2]), "+f"((C)[3])               \
        : "r"((A)[0]), "r"((A)[1]), "r"((A)[2]), "r"((A)[3]),                  \
          "r"(B0), "r"(B1))

// smem tile: 128 rows x 64B (32 bf16), 16B chunks XOR-swizzled
__device__ __forceinline__ uint32_t swz(int r, int c) {
    return (uint32_t)(r * 64 + ((c ^ ((r >> 1) & 3)) * 16));
}

// ---------------------------------------------------------------------------
// split x -> (hi, lo) bf16 row-major [M][2048]
// ---------------------------------------------------------------------------
__global__ void __launch_bounds__(256) splitx_kernel(const float* __restrict__ x, int M) {
    size_t idx = (size_t)blockIdx.x * 256 + threadIdx.x;
    size_t m = idx >> 8;
    if (m >= (size_t)M) return;
    int k = (int)(idx & 255) << 3;

    const float4* src = (const float4*)(x + m * D_DIM + k);
    float4 a = src[0], b = src[1];
    float f[8] = {a.x, a.y, a.z, a.w, b.x, b.y, b.z, b.w};

    union { __nv_bfloat16 h[8]; uint4 v; } ph, pl;
#pragma unroll
    for (int i = 0; i < 8; i++) {
        __nv_bfloat16 hi = __float2bfloat16(f[i]);
        ph.h[i] = hi;
        pl.h[i] = __float2bfloat16(f[i] - __bfloat162float(hi));
    }
    size_t off = m * (D_DIM * 2) + (size_t)k * 2;
    *(uint4*)(g_xhi + off) = ph.v;
    *(uint4*)(g_xlo + off) = pl.v;
}

// ---------------------------------------------------------------------------
// split + transpose W [2048,256] -> [256][2048] (hi, lo) bf16
// ---------------------------------------------------------------------------
__global__ void __launch_bounds__(256) splitw_kernel(const float* __restrict__ W) {
    int idx = blockIdx.x * 256 + threadIdx.x;
    int n = idx >> 8;
    int k = (idx & 255) << 3;

    union { __nv_bfloat16 h[8]; uint4 v; } ph, pl;
#pragma unroll
    for (int i = 0; i < 8; i++) {
        float f = W[(size_t)(k + i) * EMB + n];
        __nv_bfloat16 hi = __float2bfloat16(f);
        ph.h[i] = hi;
        pl.h[i] = __float2bfloat16(f - __bfloat162float(hi));
    }
    size_t off = (size_t)n * (D_DIM * 2) + (size_t)k * 2;
    *(uint4*)(g_whi + off) = ph.v;
    *(uint4*)(g_wlo + off) = pl.v;
}

// ---------------------------------------------------------------------------
// normalize expert_emb columns (+ zero the flag counter each replay)
// ---------------------------------------------------------------------------
__global__ void embn_kernel(const float* __restrict__ emb) {
    __shared__ float red[EMB];
    int e = blockIdx.x;
    int t = threadIdx.x;
    if (e == 0 && t == 0) g_nflag = 0;
    float v = emb[(size_t)t * E_EXP + e];
    red[t] = v * v;
    __syncthreads();
#pragma unroll
    for (int s = 128; s > 0; s >>= 1) {
        if (t < s) red[t] += red[t + s];
        __syncthreads();
    }
    float inv = 1.0f / sqrtf(red[0] + 1e-12f);
    g_embn[(size_t)t * E_EXP + e] = v * inv;
}

// ---------------------------------------------------------------------------
// mma.sync split-bf16 GEMM: proj[M,256] = x @ W   (identical to R5)
// ---------------------------------------------------------------------------
#define NSTAGE      3
#define STAGE_BYTES 32768u
#define OFF_ALO     8192u
#define OFF_BHI     16384u
#define OFF_BLO     24576u
#define NKT         (D_DIM / 32)

__global__ void __launch_bounds__(256) mma_gemm_kernel(int M) {
    extern __shared__ __align__(128) unsigned char smem[];
    uint32_t sb = smem_u32(smem);
    int tid  = threadIdx.x;
    int lane = tid & 31;
    int w    = tid >> 5;
    int mw   = w & 3;
    int nw   = w >> 2;

    size_t bm = (size_t)blockIdx.y * 128;
    int    bn = blockIdx.x * 128;

    int lr = tid >> 1;
    int lc = (tid & 1) * 2;
    size_t arow = (bm + lr) * (D_DIM * 2);
    size_t brow = ((size_t)(bn + lr)) * (D_DIM * 2);

    auto stage_load = [&](int kt, int s) {
        uint32_t st = sb + (uint32_t)s * STAGE_BYTES;
        size_t gk = (size_t)kt * 64;
#pragma unroll
        for (int c = lc; c < lc + 2; c++) {
            uint32_t so = swz(lr, c);
            size_t go = gk + (size_t)c * 16;
            cp16(st + so,           g_xhi + arow + go);
            cp16(st + OFF_ALO + so, g_xlo + arow + go);
            cp16(st + OFF_BHI + so, g_whi + brow + go);
            cp16(st + OFF_BLO + so, g_wlo + brow + go);
        }
        CP_COMMIT();
    };

    stage_load(0, 0);
    stage_load(1, 1);

    float acc[2][8][4];
#pragma unroll
    for (int i = 0; i < 2; i++)
#pragma unroll
        for (int j = 0; j < 8; j++)
#pragma unroll
            for (int q = 0; q < 4; q++) acc[i][j][q] = 0.0f;

    int a_r = (lane & 15);
    int a_cb = (lane >> 4);
    int b_r = (lane & 7) + ((lane >> 4) & 1) * 8;
    int b_cb = (lane >> 3) & 1;

    for (int kt = 0; kt < NKT; kt++) {
        CP_WAIT(NSTAGE - 2);
        __syncthreads();
        if (kt + NSTAGE - 1 < NKT) stage_load(kt + NSTAGE - 1, (kt + NSTAGE - 1) % NSTAGE);

        uint32_t st = sb + (uint32_t)(kt % NSTAGE) * STAGE_BYTES;

#pragma unroll
        for (int kh = 0; kh < 2; kh++) {
            uint32_t ahi[2][4], alo[2][4];
#pragma unroll
            for (int i = 0; i < 2; i++) {
                int r = mw * 32 + i * 16 + a_r;
                uint32_t ad = st + swz(r, 2 * kh + a_cb);
                LDSM4(ahi[i], ad);
                LDSM4(alo[i], ad + OFF_ALO);
            }
            uint32_t bhi[4][4], blo[4][4];
#pragma unroll
            for (int j2 = 0; j2 < 4; j2++) {
                int r = nw * 64 + j2 * 16 + b_r;
                uint32_t ad = st + OFF_BHI + swz(r, 2 * kh + b_cb);
                LDSM4(bhi[j2], ad);
                LDSM4(blo[j2], ad + 8192);
            }
#pragma unroll
            for (int i = 0; i < 2; i++) {
#pragma unroll
                for (int j = 0; j < 8; j++) {
                    uint32_t* bh = &bhi[j >> 1][(j & 1) * 2];
                    uint32_t* bl = &blo[j >> 1][(j & 1) * 2];
                    MMA16816(acc[i][j], ahi[i], bh[0], bh[1]);
                    MMA16816(acc[i][j], ahi[i], bl[0], bl[1]);
                    MMA16816(acc[i][j], alo[i], bh[0], bh[1]);
                }
            }
        }
    }

#pragma unroll
    for (int i = 0; i < 2; i++) {
#pragma unroll
        for (int j = 0; j < 8; j++) {
            size_t r0 = bm + mw * 32 + i * 16 + (lane >> 2);
            int col = bn + nw * 64 + j * 8 + 2 * (lane & 3);
            *(float2*)&g_proj[r0 * EMB + col] =
                make_float2(acc[i][j][0], acc[i][j][1]);
            *(float2*)&g_proj[(r0 + 8) * EMB + col] =
                make_float2(acc[i][j][2], acc[i][j][3]);
        }
    }
}

// ---------------------------------------------------------------------------
// Gate kernel: + top-3 gap computation, flags near-tie rows for refinement
// ---------------------------------------------------------------------------
__global__ void __launch_bounds__(256) gate_kernel(
        const float* __restrict__ tptr, float* __restrict__ out, int M) {
    extern __shared__ float sh[];
    float2* s_emb = (float2*)sh;
    int tid = threadIdx.x;
    int lane = tid & 31;
    int warp = tid >> 5;
    float* s_proj = sh + EMB * E_EXP + warp * EMB;

    for (int i = tid; i < EMB * 32; i += 256) {
        int k = i >> 5;
        int l = i & 31;
        s_emb[i] = make_float2(g_embn[k * 64 + l], g_embn[k * 64 + l + 32]);
    }
    __syncthreads();

    float temp = tptr[0];
    size_t nM = (size_t)M;
    float* out_ew  = out;
    float* out_ti  = out + nM * 64;
    float* out_lg  = out + nM * 66;
    float* out_cs  = out + nM * 130;
    float* out_raw = out + nM * 194;

    int gw = blockIdx.x * 8 + warp;
    int nw = gridDim.x * 8;

    for (int r = gw; r < M; r += nw) {
        const float4* pr = (const float4*)(g_proj + (size_t)r * EMB);
        float4 v0 = pr[lane];
        float4 v1 = pr[lane + 32];
        float ss = v0.x * v0.x + v0.y * v0.y + v0.z * v0.z + v0.w * v0.w
                 + v1.x * v1.x + v1.y * v1.y + v1.z * v1.z + v1.w * v1.w;
#pragma unroll
        for (int off = 16; off > 0; off >>= 1)
            ss += __shfl_xor_sync(0xffffffffu, ss, off);
        float inv = 1.0f / sqrtf(ss + 1e-12f);

        float4 n0 = make_float4(v0.x * inv, v0.y * inv, v0.z * inv, v0.w * inv);
        float4 n1 = make_float4(v1.x * inv, v1.y * inv, v1.z * inv, v1.w * inv);
        ((float4*)s_proj)[lane] = n0;
        ((float4*)s_proj)[lane + 32] = n1;
        __syncwarp();

        float c0 = 0.0f, c1 = 0.0f;
#pragma unroll 8
        for (int k = 0; k < EMB; k++) {
            float pn = s_proj[k];
            float2 e2 = s_emb[k * 32 + lane];
            c0 = fmaf(pn, e2.x, c0);
            c1 = fmaf(pn, e2.y, c1);
        }
        __syncwarp();

        float l0 = c0 * temp;
        float l1 = c1 * temp;

        float bv = l0; int bi = lane;
        if (l1 > bv) { bv = l1; bi = lane + 32; }
#pragma unroll
        for (int off = 16; off > 0; off >>= 1) {
            float ov = __shfl_xor_sync(0xffffffffu, bv, off);
            int   oi = __shfl_xor_sync(0xffffffffu, bi, off);
            if (ov > bv || (ov == bv && oi < bi)) { bv = ov; bi = oi; }
        }
        float t1v = bv; int t1i = bi;

        float m0 = (lane == t1i)      ? -INFINITY : l0;
        float m1 = (lane + 32 == t1i) ? -INFINITY : l1;
        bv = m0; bi = lane;
        if (m1 > bv || (m1 == bv && (lane + 32) < bi)) { bv = m1; bi = lane + 32; }
#pragma unroll
        for (int off = 16; off > 0; off >>= 1) {
            float ov = __shfl_xor_sync(0xffffffffu, bv, off);
            int   oi = __shfl_xor_sync(0xffffffffu, bi, off);
            if (ov > bv || (ov == bv && oi < bi)) { bv = ov; bi = oi; }
        }
        float t2v = bv; int t2i = bi;

        // third-highest value (for tie-gap flagging)
        float p0 = (lane == t1i || lane == t2i) ? -INFINITY : l0;
        float p1 = (lane + 32 == t1i || lane + 32 == t2i) ? -INFINITY : l1;
        float t3v = fmaxf(p0, p1);
#pragma unroll
        for (int off = 16; off > 0; off >>= 1)
            t3v = fmaxf(t3v, __shfl_xor_sync(0xffffffffu, t3v, off));

        float ex0 = expf(l0 - t1v);
        float ex1 = expf(l1 - t1v);
        float tot = ex0 + ex1;
#pragma unroll
        for (int off = 16; off > 0; off >>= 1)
            tot += __shfl_xor_sync(0xffffffffu, tot, off);
        float r0 = ex0 / tot;
        float r1 = ex1 / tot;

        float eT = expf(t2v - t1v);
        float denom = 1.0f + eT;
        float w1 = 1.0f / denom;
        float w2 = eT / denom;
        float ew0 = (lane == t1i) ? w1 : ((lane == t2i) ? w2 : 0.0f);
        float ew1 = (lane + 32 == t1i) ? w1 : ((lane + 32 == t2i) ? w2 : 0.0f);

        size_t ro = (size_t)r * 64;
        out_ew[ro + lane]       = ew0;
        out_ew[ro + lane + 32]  = ew1;
        out_lg[ro + lane]       = l0;
        out_lg[ro + lane + 32]  = l1;
        out_cs[ro + lane]       = c0;
        out_cs[ro + lane + 32]  = c1;
        out_raw[ro + lane]      = r0;
        out_raw[ro + lane + 32] = r1;
        if (lane == 0) {
            out_ti[(size_t)r * 2]     = (float)t1i;
            out_ti[(size_t)r * 2 + 1] = (float)t2i;
            if ((t1v - t2v) < THETA || (t2v - t3v) < THETA) {
                int fi = atomicAdd(&g_nflag, 1);
                if (fi < MAXFLAG) g_flagrows[fi] = r;
            }
        }
    }
}

// ---------------------------------------------------------------------------
// Refinement: recompute flagged rows in exact fp32 and overwrite outputs.
// One block (256 threads) per flagged row.
// ---------------------------------------------------------------------------
__global__ void __launch_bounds__(256) refine_kernel(
        const float* __restrict__ x, const float* __restrict__ W,
        const float* __restrict__ tptr, float* __restrict__ out, int M) {
    __shared__ float sx[D_DIM];
    __shared__ float sp[EMB];
    __shared__ float sred[256];
    __shared__ float scos[E_EXP];
    __shared__ float sres[E_EXP * 2 + 8];   // ew, raw, [t1i,t2i,l@e...]

    int b = blockIdx.x;
    if (b >= g_nflag) return;
    int r = g_flagrows[b];
    int t = threadIdx.x;

    for (int i = t; i < D_DIM; i += 256) sx[i] = x[(size_t)r * D_DIM + i];
    __syncthreads();

    float acc = 0.0f;
#pragma unroll 8
    for (int k = 0; k < D_DIM; k++)
        acc = fmaf(sx[k], W[(size_t)k * EMB + t], acc);
    sp[t] = acc;
    sred[t] = acc * acc;
    __syncthreads();
#pragma unroll
    for (int s = 128; s > 0; s >>= 1) {
        if (t < s) sred[t] += sred[t + s];
        __syncthreads();
    }
    float inv = 1.0f / sqrtf(sred[0] + 1e-12f);

    if (t < E_EXP) {
        float c = 0.0f;
#pragma unroll 8
        for (int k = 0; k < EMB; k++)
            c = fmaf(sp[k] * inv, g_embn[k * E_EXP + t], c);
        scos[t] = c;
    }
    __syncthreads();

    float temp = tptr[0];
    if (t == 0) {
        // serial top-2 (lowest index wins ties), softmaxes
        float t1v = scos[0] * temp; int t1i = 0;
        for (int e = 1; e < E_EXP; e++) {
            float l = scos[e] * temp;
            if (l > t1v) { t1v = l; t1i = e; }
        }
        float t2v = -INFINITY; int t2i = 0;
        for (int e = 0; e < E_EXP; e++) {
            if (e == t1i) continue;
            float l = scos[e] * temp;
            if (l > t2v) { t2v = l; t2i = e; }
        }
        float tot = 0.0f;
        for (int e = 0; e < E_EXP; e++) tot += expf(scos[e] * temp - t1v);

        float eT = expf(t2v - t1v);
        float denom = 1.0f + eT;
        float w1 = 1.0f / denom;
        float w2 = eT / denom;
        for (int e = 0; e < E_EXP; e++) {
            float l = scos[e] * temp;
            sres[e] = (e == t1i) ? w1 : ((e == t2i) ? w2 : 0.0f);   // ew
            sres[E_EXP + e] = expf(l - t1v) / tot;                  // raw
        }
        sres[2 * E_EXP]     = (float)t1i;
        sres[2 * E_EXP + 1] = (float)t2i;
    }
    __syncthreads();

    size_t nM = (size_t)M;
    size_t ro = (size_t)r * 64;
    if (t < E_EXP) {
        float c = scos[t];
        out[ro + t]                 = sres[t];             // expert_weights
        out[nM * 66 + ro + t]       = c * temp;            // logits
        out[nM * 130 + ro + t]      = c;                   // cos
        out[nM * 194 + ro + t]      = sres[E_EXP + t];     // raw
    }
    if (t == 0) {
        out[nM * 64 + (size_t)r * 2]     = sres[2 * E_EXP];
        out[nM * 64 + (size_t)r * 2 + 1] = sres[2 * E_EXP + 1];
    }
}

// ---------------------------------------------------------------------------
extern "C" void kernel_launch(void* const* d_in, const int* in_sizes, int n_in,
                              void* d_out, int out_size) {
    const float* x    = (const float*)d_in[0];   // [N, 2048]
    const float* W    = (const float*)d_in[1];   // [2048, 256]
    const float* emb  = (const float*)d_in[2];   // [256, 64]
    const float* temp = (const float*)d_in[3];   // [1]
    float* out = (float*)d_out;

    int M = in_sizes[0] / D_DIM;

    splitx_kernel<<<M, 256>>>(x, M);
    splitw_kernel<<<256, 256>>>(W);
    embn_kernel<<<E_EXP, EMB>>>(emb);

    int gsmem = NSTAGE * (int)STAGE_BYTES;   // 98304 B
    cudaFuncSetAttribute(mma_gemm_kernel,
                         cudaFuncAttributeMaxDynamicSharedMemorySize, gsmem);
    dim3 grid(EMB / 128, M / 128);
    mma_gemm_kernel<<<grid, 256, gsmem>>>(M);

    int smem = (EMB * E_EXP + 8 * EMB) * (int)sizeof(float);
    cudaFuncSetAttribute(gate_kernel, cudaFuncAttributeMaxDynamicSharedMemorySize, smem);
    gate_kernel<<<444, 256, smem>>>(temp, out, M);

    refine_kernel<<<MAXFLAG, 256>>>(x, W, temp, out, M);
}

// round 7
// speedup vs baseline: 1.2580x; 1.0785x over previous
#include <cuda_runtime.h>
#include <cuda_bf16.h>
#include <math.h>
#include <stdint.h>

#define D_DIM 2048
#define EMB   256
#define E_EXP 64
#define MAX_N 65536
#define THETA 2e-4f
#define MAXFLAG 8192
#define RB 8                       // refine rows per block

// ---------------------------------------------------------------------------
// Device-global scratch (no allocations allowed)
// ---------------------------------------------------------------------------
__device__ float g_proj[(size_t)MAX_N * EMB];
__device__ float g_embn[EMB * E_EXP];
__device__ int   g_nflag;
__device__ int   g_flagrows[MAXFLAG];

__device__ __align__(128) unsigned char g_xhi[(size_t)MAX_N * D_DIM * 2];
__device__ __align__(128) unsigned char g_xlo[(size_t)MAX_N * D_DIM * 2];
__device__ __align__(128) unsigned char g_whi[(size_t)EMB * D_DIM * 2];
__device__ __align__(128) unsigned char g_wlo[(size_t)EMB * D_DIM * 2];

// ---------------------------------------------------------------------------
// Base-ISA PTX helpers
// ---------------------------------------------------------------------------
__device__ __forceinline__ uint32_t smem_u32(const void* p) {
    uint32_t a;
    asm("{ .reg .u64 t; cvta.to.shared.u64 t, %1; cvt.u32.u64 %0, t; }"
        : "=r"(a) : "l"(p));
    return a;
}
__device__ __forceinline__ void cp16(uint32_t s, const void* g) {
    asm volatile("cp.async.cg.shared.global [%0], [%1], 16;"
                 :: "r"(s), "l"(g) : "memory");
}
#define CP_COMMIT() asm volatile("cp.async.commit_group;" ::: "memory")
#define CP_WAIT(n)  asm volatile("cp.async.wait_group %0;" :: "n"(n) : "memory")

#define LDSM4(R, a)                                                            \
    asm volatile("ldmatrix.sync.aligned.m8n8.x4.shared.b16 {%0,%1,%2,%3}, [%4];" \
        : "=r"((R)[0]), "=r"((R)[1]), "=r"((R)[2]), "=r"((R)[3]) : "r"(a))

#define MMA16816(C, A, B0, B1)                                                 \
    asm volatile(                                                              \
        "mma.sync.aligned.m16n8k16.row.col.f32.bf16.bf16.f32 "                 \
        "{%0,%1,%2,%3}, {%4,%5,%6,%7}, {%8,%9}, {%0,%1,%2,%3};"                \
        : "+f"((C)[0]), "+f"((C)[1]), "+f"((C)[2]), "+f"((C)[3])               \
        : "r"((A)[0]), "r"((A)[1]), "r"((A)[2]), "r"((A)[3]),                  \
          "r"(B0), "r"(B1))

__device__ __forceinline__ uint32_t swz(int r, int c) {
    return (uint32_t)(r * 64 + ((c ^ ((r >> 1) & 3)) * 16));
}

// ---------------------------------------------------------------------------
// split x -> (hi, lo) bf16 row-major [M][2048]
// ---------------------------------------------------------------------------
__global__ void __launch_bounds__(256) splitx_kernel(const float* __restrict__ x, int M) {
    size_t idx = (size_t)blockIdx.x * 256 + threadIdx.x;
    size_t m = idx >> 8;
    if (m >= (size_t)M) return;
    int k = (int)(idx & 255) << 3;

    const float4* src = (const float4*)(x + m * D_DIM + k);
    float4 a = src[0], b = src[1];
    float f[8] = {a.x, a.y, a.z, a.w, b.x, b.y, b.z, b.w};

    union { __nv_bfloat16 h[8]; uint4 v; } ph, pl;
#pragma unroll
    for (int i = 0; i < 8; i++) {
        __nv_bfloat16 hi = __float2bfloat16(f[i]);
        ph.h[i] = hi;
        pl.h[i] = __float2bfloat16(f[i] - __bfloat162float(hi));
    }
    size_t off = m * (D_DIM * 2) + (size_t)k * 2;
    *(uint4*)(g_xhi + off) = ph.v;
    *(uint4*)(g_xlo + off) = pl.v;
}

// ---------------------------------------------------------------------------
// split + transpose W [2048,256] -> [256][2048] (hi, lo) bf16
// ---------------------------------------------------------------------------
__global__ void __launch_bounds__(256) splitw_kernel(const float* __restrict__ W) {
    int idx = blockIdx.x * 256 + threadIdx.x;
    int n = idx >> 8;
    int k = (idx & 255) << 3;

    union { __nv_bfloat16 h[8]; uint4 v; } ph, pl;
#pragma unroll
    for (int i = 0; i < 8; i++) {
        float f = W[(size_t)(k + i) * EMB + n];
        __nv_bfloat16 hi = __float2bfloat16(f);
        ph.h[i] = hi;
        pl.h[i] = __float2bfloat16(f - __bfloat162float(hi));
    }
    size_t off = (size_t)n * (D_DIM * 2) + (size_t)k * 2;
    *(uint4*)(g_whi + off) = ph.v;
    *(uint4*)(g_wlo + off) = pl.v;
}

// ---------------------------------------------------------------------------
// normalize expert_emb columns (+ zero flag counter each replay)
// ---------------------------------------------------------------------------
__global__ void embn_kernel(const float* __restrict__ emb) {
    __shared__ float red[EMB];
    int e = blockIdx.x;
    int t = threadIdx.x;
    if (e == 0 && t == 0) g_nflag = 0;
    float v = emb[(size_t)t * E_EXP + e];
    red[t] = v * v;
    __syncthreads();
#pragma unroll
    for (int s = 128; s > 0; s >>= 1) {
        if (t < s) red[t] += red[t + s];
        __syncthreads();
    }
    float inv = 1.0f / sqrtf(red[0] + 1e-12f);
    g_embn[(size_t)t * E_EXP + e] = v * inv;
}

// ---------------------------------------------------------------------------
// mma.sync split-bf16 GEMM — now 2 CTAs/SM (reg-capped at 128)
// ---------------------------------------------------------------------------
#define NSTAGE      3
#define STAGE_BYTES 32768u
#define OFF_ALO     8192u
#define OFF_BHI     16384u
#define OFF_BLO     24576u
#define NKT         (D_DIM / 32)

__global__ void __launch_bounds__(256, 2) mma_gemm_kernel(int M) {
    extern __shared__ __align__(128) unsigned char smem[];
    uint32_t sb = smem_u32(smem);
    int tid  = threadIdx.x;
    int lane = tid & 31;
    int w    = tid >> 5;
    int mw   = w & 3;
    int nw   = w >> 2;

    size_t bm = (size_t)blockIdx.y * 128;
    int    bn = blockIdx.x * 128;

    int lr = tid >> 1;
    int lc = (tid & 1) * 2;
    size_t arow = (bm + lr) * (D_DIM * 2);
    size_t brow = ((size_t)(bn + lr)) * (D_DIM * 2);

    auto stage_load = [&](int kt, int s) {
        uint32_t st = sb + (uint32_t)s * STAGE_BYTES;
        size_t gk = (size_t)kt * 64;
#pragma unroll
        for (int c = lc; c < lc + 2; c++) {
            uint32_t so = swz(lr, c);
            size_t go = gk + (size_t)c * 16;
            cp16(st + so,           g_xhi + arow + go);
            cp16(st + OFF_ALO + so, g_xlo + arow + go);
            cp16(st + OFF_BHI + so, g_whi + brow + go);
            cp16(st + OFF_BLO + so, g_wlo + brow + go);
        }
        CP_COMMIT();
    };

    stage_load(0, 0);
    stage_load(1, 1);

    float acc[2][8][4];
#pragma unroll
    for (int i = 0; i < 2; i++)
#pragma unroll
        for (int j = 0; j < 8; j++)
#pragma unroll
            for (int q = 0; q < 4; q++) acc[i][j][q] = 0.0f;

    int a_r = (lane & 15);
    int a_cb = (lane >> 4);
    int b_r = (lane & 7) + ((lane >> 4) & 1) * 8;
    int b_cb = (lane >> 3) & 1;

    for (int kt = 0; kt < NKT; kt++) {
        CP_WAIT(NSTAGE - 2);
        __syncthreads();
        if (kt + NSTAGE - 1 < NKT) stage_load(kt + NSTAGE - 1, (kt + NSTAGE - 1) % NSTAGE);

        uint32_t st = sb + (uint32_t)(kt % NSTAGE) * STAGE_BYTES;

#pragma unroll
        for (int kh = 0; kh < 2; kh++) {
            uint32_t ahi[2][4], alo[2][4];
#pragma unroll
            for (int i = 0; i < 2; i++) {
                int r = mw * 32 + i * 16 + a_r;
                uint32_t ad = st + swz(r, 2 * kh + a_cb);
                LDSM4(ahi[i], ad);
                LDSM4(alo[i], ad + OFF_ALO);
            }
            uint32_t bhi[4][4], blo[4][4];
#pragma unroll
            for (int j2 = 0; j2 < 4; j2++) {
                int r = nw * 64 + j2 * 16 + b_r;
                uint32_t ad = st + OFF_BHI + swz(r, 2 * kh + b_cb);
                LDSM4(bhi[j2], ad);
                LDSM4(blo[j2], ad + 8192);
            }
#pragma unroll
            for (int i = 0; i < 2; i++) {
#pragma unroll
                for (int j = 0; j < 8; j++) {
                    uint32_t* bh = &bhi[j >> 1][(j & 1) * 2];
                    uint32_t* bl = &blo[j >> 1][(j & 1) * 2];
                    MMA16816(acc[i][j], ahi[i], bh[0], bh[1]);
                    MMA16816(acc[i][j], ahi[i], bl[0], bl[1]);
                    MMA16816(acc[i][j], alo[i], bh[0], bh[1]);
                }
            }
        }
    }

#pragma unroll
    for (int i = 0; i < 2; i++) {
#pragma unroll
        for (int j = 0; j < 8; j++) {
            size_t r0 = bm + mw * 32 + i * 16 + (lane >> 2);
            int col = bn + nw * 64 + j * 8 + 2 * (lane & 3);
            *(float2*)&g_proj[r0 * EMB + col] =
                make_float2(acc[i][j][0], acc[i][j][1]);
            *(float2*)&g_proj[(r0 + 8) * EMB + col] =
                make_float2(acc[i][j][2], acc[i][j][3]);
        }
    }
}

// ---------------------------------------------------------------------------
// Gate kernel: emits outputs + flags near-tie rows for exact refinement
// ---------------------------------------------------------------------------
__global__ void __launch_bounds__(256) gate_kernel(
        const float* __restrict__ tptr, float* __restrict__ out, int M) {
    extern __shared__ float sh[];
    float2* s_emb = (float2*)sh;
    int tid = threadIdx.x;
    int lane = tid & 31;
    int warp = tid >> 5;
    float* s_proj = sh + EMB * E_EXP + warp * EMB;

    for (int i = tid; i < EMB * 32; i += 256) {
        int k = i >> 5;
        int l = i & 31;
        s_emb[i] = make_float2(g_embn[k * 64 + l], g_embn[k * 64 + l + 32]);
    }
    __syncthreads();

    float temp = tptr[0];
    size_t nM = (size_t)M;
    float* out_ew  = out;
    float* out_ti  = out + nM * 64;
    float* out_lg  = out + nM * 66;
    float* out_cs  = out + nM * 130;
    float* out_raw = out + nM * 194;

    int gw = blockIdx.x * 8 + warp;
    int nw = gridDim.x * 8;

    for (int r = gw; r < M; r += nw) {
        const float4* pr = (const float4*)(g_proj + (size_t)r * EMB);
        float4 v0 = pr[lane];
        float4 v1 = pr[lane + 32];
        float ss = v0.x * v0.x + v0.y * v0.y + v0.z * v0.z + v0.w * v0.w
                 + v1.x * v1.x + v1.y * v1.y + v1.z * v1.z + v1.w * v1.w;
#pragma unroll
        for (int off = 16; off > 0; off >>= 1)
            ss += __shfl_xor_sync(0xffffffffu, ss, off);
        float inv = 1.0f / sqrtf(ss + 1e-12f);

        float4 n0 = make_float4(v0.x * inv, v0.y * inv, v0.z * inv, v0.w * inv);
        float4 n1 = make_float4(v1.x * inv, v1.y * inv, v1.z * inv, v1.w * inv);
        ((float4*)s_proj)[lane] = n0;
        ((float4*)s_proj)[lane + 32] = n1;
        __syncwarp();

        float c0 = 0.0f, c1 = 0.0f;
#pragma unroll 8
        for (int k = 0; k < EMB; k++) {
            float pn = s_proj[k];
            float2 e2 = s_emb[k * 32 + lane];
            c0 = fmaf(pn, e2.x, c0);
            c1 = fmaf(pn, e2.y, c1);
        }
        __syncwarp();

        float l0 = c0 * temp;
        float l1 = c1 * temp;

        float bv = l0; int bi = lane;
        if (l1 > bv) { bv = l1; bi = lane + 32; }
#pragma unroll
        for (int off = 16; off > 0; off >>= 1) {
            float ov = __shfl_xor_sync(0xffffffffu, bv, off);
            int   oi = __shfl_xor_sync(0xffffffffu, bi, off);
            if (ov > bv || (ov == bv && oi < bi)) { bv = ov; bi = oi; }
        }
        float t1v = bv; int t1i = bi;

        float m0 = (lane == t1i)      ? -INFINITY : l0;
        float m1 = (lane + 32 == t1i) ? -INFINITY : l1;
        bv = m0; bi = lane;
        if (m1 > bv || (m1 == bv && (lane + 32) < bi)) { bv = m1; bi = lane + 32; }
#pragma unroll
        for (int off = 16; off > 0; off >>= 1) {
            float ov = __shfl_xor_sync(0xffffffffu, bv, off);
            int   oi = __shfl_xor_sync(0xffffffffu, bi, off);
            if (ov > bv || (ov == bv && oi < bi)) { bv = ov; bi = oi; }
        }
        float t2v = bv; int t2i = bi;

        float p0 = (lane == t1i || lane == t2i) ? -INFINITY : l0;
        float p1 = (lane + 32 == t1i || lane + 32 == t2i) ? -INFINITY : l1;
        float t3v = fmaxf(p0, p1);
#pragma unroll
        for (int off = 16; off > 0; off >>= 1)
            t3v = fmaxf(t3v, __shfl_xor_sync(0xffffffffu, t3v, off));

        float ex0 = expf(l0 - t1v);
        float ex1 = expf(l1 - t1v);
        float tot = ex0 + ex1;
#pragma unroll
        for (int off = 16; off > 0; off >>= 1)
            tot += __shfl_xor_sync(0xffffffffu, tot, off);
        float r0 = ex0 / tot;
        float r1 = ex1 / tot;

        float eT = expf(t2v - t1v);
        float denom = 1.0f + eT;
        float w1 = 1.0f / denom;
        float w2 = eT / denom;
        float ew0 = (lane == t1i) ? w1 : ((lane == t2i) ? w2 : 0.0f);
        float ew1 = (lane + 32 == t1i) ? w1 : ((lane + 32 == t2i) ? w2 : 0.0f);

        size_t ro = (size_t)r * 64;
        out_ew[ro + lane]       = ew0;
        out_ew[ro + lane + 32]  = ew1;
        out_lg[ro + lane]       = l0;
        out_lg[ro + lane + 32]  = l1;
        out_cs[ro + lane]       = c0;
        out_cs[ro + lane + 32]  = c1;
        out_raw[ro + lane]      = r0;
        out_raw[ro + lane + 32] = r1;
        if (lane == 0) {
            out_ti[(size_t)r * 2]     = (float)t1i;
            out_ti[(size_t)r * 2 + 1] = (float)t2i;
            if ((t1v - t2v) < THETA || (t2v - t3v) < THETA) {
                int fi = atomicAdd(&g_nflag, 1);
                if (fi < MAXFLAG) g_flagrows[fi] = r;
            }
        }
    }
}

// ---------------------------------------------------------------------------
// Refinement: RB flagged rows per block — W read once, reused RB times.
// Phase 1: all 256 threads compute proj col t for all RB rows (x in smem).
// Phase 2: warp w handles row w (sumsq + cos + gating), identical math.
// ---------------------------------------------------------------------------
__global__ void __launch_bounds__(256) refine_kernel(
        const float* __restrict__ x, const float* __restrict__ W,
        const float* __restrict__ tptr, float* __restrict__ out, int M) {
    extern __shared__ float rsh[];
    float* sx = rsh;                    // [RB][2048]
    float* sp = rsh + RB * D_DIM;       // [RB][256]

    int nf = g_nflag;
    if (nf > MAXFLAG) nf = MAXFLAG;
    int base = blockIdx.x * RB;
    if (base >= nf) return;
    int nr = nf - base;
    if (nr > RB) nr = RB;

    int t = threadIdx.x;
    int rows[RB];
#pragma unroll
    for (int lr = 0; lr < RB; lr++) {
        int fi = base + (lr < nr ? lr : nr - 1);   // duplicate last valid row
        rows[lr] = g_flagrows[fi];
    }
    for (int lr = 0; lr < RB; lr++)
        for (int i = t; i < D_DIM; i += 256)
            sx[lr * D_DIM + i] = x[(size_t)rows[lr] * D_DIM + i];
    __syncthreads();

    float acc[RB];
#pragma unroll
    for (int lr = 0; lr < RB; lr++) acc[lr] = 0.0f;
#pragma unroll 4
    for (int k = 0; k < D_DIM; k++) {
        float wv = W[(size_t)k * EMB + t];
#pragma unroll
        for (int lr = 0; lr < RB; lr++)
            acc[lr] = fmaf(sx[lr * D_DIM + k], wv, acc[lr]);
    }
#pragma unroll
    for (int lr = 0; lr < RB; lr++) sp[lr * EMB + t] = acc[lr];
    __syncthreads();

    int w = t >> 5, lane = t & 31;
    if (w < nr) {
        int r = rows[w];
        const float* rp = sp + w * EMB;

        float ss = 0.0f;
#pragma unroll
        for (int i = 0; i < 8; i++) {
            float v = rp[i * 32 + lane];
            ss = fmaf(v, v, ss);
        }
#pragma unroll
        for (int off = 16; off > 0; off >>= 1)
            ss += __shfl_xor_sync(0xffffffffu, ss, off);
        float inv = 1.0f / sqrtf(ss + 1e-12f);

        float c0 = 0.0f, c1 = 0.0f;
#pragma unroll 8
        for (int k = 0; k < EMB; k++) {
            float pn = rp[k] * inv;
            c0 = fmaf(pn, g_embn[k * E_EXP + lane], c0);
            c1 = fmaf(pn, g_embn[k * E_EXP + lane + 32], c1);
        }

        float temp = tptr[0];
        float l0 = c0 * temp;
        float l1 = c1 * temp;

        float bv = l0; int bi = lane;
        if (l1 > bv) { bv = l1; bi = lane + 32; }
#pragma unroll
        for (int off = 16; off > 0; off >>= 1) {
            float ov = __shfl_xor_sync(0xffffffffu, bv, off);
            int   oi = __shfl_xor_sync(0xffffffffu, bi, off);
            if (ov > bv || (ov == bv && oi < bi)) { bv = ov; bi = oi; }
        }
        float t1v = bv; int t1i = bi;

        float m0 = (lane == t1i)      ? -INFINITY : l0;
        float m1 = (lane + 32 == t1i) ? -INFINITY : l1;
        bv = m0; bi = lane;
        if (m1 > bv || (m1 == bv && (lane + 32) < bi)) { bv = m1; bi = lane + 32; }
#pragma unroll
        for (int off = 16; off > 0; off >>= 1) {
            float ov = __shfl_xor_sync(0xffffffffu, bv, off);
            int   oi = __shfl_xor_sync(0xffffffffu, bi, off);
            if (ov > bv || (ov == bv && oi < bi)) { bv = ov; bi = oi; }
        }
        float t2v = bv; int t2i = bi;

        float ex0 = expf(l0 - t1v);
        float ex1 = expf(l1 - t1v);
        float tot = ex0 + ex1;
#pragma unroll
        for (int off = 16; off > 0; off >>= 1)
            tot += __shfl_xor_sync(0xffffffffu, tot, off);
        float r0 = ex0 / tot;
        float r1 = ex1 / tot;

        float eT = expf(t2v - t1v);
        float denom = 1.0f + eT;
        float w1 = 1.0f / denom;
        float w2 = eT / denom;
        float ew0 = (lane == t1i) ? w1 : ((lane == t2i) ? w2 : 0.0f);
        float ew1 = (lane + 32 == t1i) ? w1 : ((lane + 32 == t2i) ? w2 : 0.0f);

        size_t nM = (size_t)M;
        size_t ro = (size_t)r * 64;
        out[ro + lane]              = ew0;
        out[ro + lane + 32]         = ew1;
        out[nM * 66 + ro + lane]    = l0;
        out[nM * 66 + ro + lane + 32]  = l1;
        out[nM * 130 + ro + lane]   = c0;
        out[nM * 130 + ro + lane + 32] = c1;
        out[nM * 194 + ro + lane]   = r0;
        out[nM * 194 + ro + lane + 32] = r1;
        if (lane == 0) {
            out[nM * 64 + (size_t)r * 2]     = (float)t1i;
            out[nM * 64 + (size_t)r * 2 + 1] = (float)t2i;
        }
    }
}

// ---------------------------------------------------------------------------
extern "C" void kernel_launch(void* const* d_in, const int* in_sizes, int n_in,
                              void* d_out, int out_size) {
    const float* x    = (const float*)d_in[0];
    const float* W    = (const float*)d_in[1];
    const float* emb  = (const float*)d_in[2];
    const float* temp = (const float*)d_in[3];
    float* out = (float*)d_out;

    int M = in_sizes[0] / D_DIM;

    splitx_kernel<<<M, 256>>>(x, M);
    splitw_kernel<<<256, 256>>>(W);
    embn_kernel<<<E_EXP, EMB>>>(emb);

    int gsmem = NSTAGE * (int)STAGE_BYTES;   // 98304 B
    cudaFuncSetAttribute(mma_gemm_kernel,
                         cudaFuncAttributeMaxDynamicSharedMemorySize, gsmem);
    dim3 grid(EMB / 128, M / 128);
    mma_gemm_kernel<<<grid, 256, gsmem>>>(M);

    int smem = (EMB * E_EXP + 8 * EMB) * (int)sizeof(float);
    cudaFuncSetAttribute(gate_kernel, cudaFuncAttributeMaxDynamicSharedMemorySize, smem);
    gate_kernel<<<444, 256, smem>>>(temp, out, M);

    int rsmem = (RB * D_DIM + RB * EMB) * (int)sizeof(float);  // 73728 B
    cudaFuncSetAttribute(refine_kernel,
                         cudaFuncAttributeMaxDynamicSharedMemorySize, rsmem);
    refine_kernel<<<(MAXFLAG + RB - 1) / RB, 256, rsmem>>>(x, W, temp, out, M);
}

// round 8
// speedup vs baseline: 1.3758x; 1.0936x over previous
#include <cuda_runtime.h>
#include <cuda_bf16.h>
#include <math.h>
#include <stdint.h>

#define D_DIM 2048
#define EMB   256
#define E_EXP 64
#define MAX_N 65536
#define THETA 2e-4f
#define MAXFLAG 8192
#define RB 8                       // refine rows per block

// ---------------------------------------------------------------------------
// Device-global scratch (no allocations allowed)
// ---------------------------------------------------------------------------
__device__ float g_proj[(size_t)MAX_N * EMB];
__device__ float g_embn[EMB * E_EXP];
__device__ int   g_nflag;
__device__ int   g_flagrows[MAXFLAG];

// Only W is pre-split (tiny). x is split in-GEMM now.
__device__ __align__(128) unsigned char g_whi[(size_t)EMB * D_DIM * 2];
__device__ __align__(128) unsigned char g_wlo[(size_t)EMB * D_DIM * 2];

// ---------------------------------------------------------------------------
// Base-ISA PTX helpers
// ---------------------------------------------------------------------------
__device__ __forceinline__ uint32_t smem_u32(const void* p) {
    uint32_t a;
    asm("{ .reg .u64 t; cvta.to.shared.u64 t, %1; cvt.u32.u64 %0, t; }"
        : "=r"(a) : "l"(p));
    return a;
}
__device__ __forceinline__ void cp16(uint32_t s, const void* g) {
    asm volatile("cp.async.cg.shared.global [%0], [%1], 16;"
                 :: "r"(s), "l"(g) : "memory");
}
#define CP_COMMIT() asm volatile("cp.async.commit_group;" ::: "memory")
#define CP_WAIT(n)  asm volatile("cp.async.wait_group %0;" :: "n"(n) : "memory")

#define LDSM4(R, a)                                                            \
    asm volatile("ldmatrix.sync.aligned.m8n8.x4.shared.b16 {%0,%1,%2,%3}, [%4];" \
        : "=r"((R)[0]), "=r"((R)[1]), "=r"((R)[2]), "=r"((R)[3]) : "r"(a))

#define MMA16816(C, A, B0, B1)                                                 \
    asm volatile(                                                              \
        "mma.sync.aligned.m16n8k16.row.col.f32.bf16.bf16.f32 "                 \
        "{%0,%1,%2,%3}, {%4,%5,%6,%7}, {%8,%9}, {%0,%1,%2,%3};"                \
        : "+f"((C)[0]), "+f"((C)[1]), "+f"((C)[2]), "+f"((C)[3])               \
        : "r"((A)[0]), "r"((A)[1]), "r"((A)[2]), "r"((A)[3]),                  \
          "r"(B0), "r"(B1))

__device__ __forceinline__ uint32_t swz(int r, int c) {
    return (uint32_t)(r * 64 + ((c ^ ((r >> 1) & 3)) * 16));
}

// ---------------------------------------------------------------------------
// split + transpose W [2048,256] -> [256][2048] (hi, lo) bf16
// ---------------------------------------------------------------------------
__global__ void __launch_bounds__(256) splitw_kernel(const float* __restrict__ W) {
    int idx = blockIdx.x * 256 + threadIdx.x;
    int n = idx >> 8;
    int k = (idx & 255) << 3;

    union { __nv_bfloat16 h[8]; uint4 v; } ph, pl;
#pragma unroll
    for (int i = 0; i < 8; i++) {
        float f = W[(size_t)(k + i) * EMB + n];
        __nv_bfloat16 hi = __float2bfloat16(f);
        ph.h[i] = hi;
        pl.h[i] = __float2bfloat16(f - __bfloat162float(hi));
    }
    size_t off = (size_t)n * (D_DIM * 2) + (size_t)k * 2;
    *(uint4*)(g_whi + off) = ph.v;
    *(uint4*)(g_wlo + off) = pl.v;
}

// ---------------------------------------------------------------------------
// normalize expert_emb columns (+ zero flag counter each replay)
// ---------------------------------------------------------------------------
__global__ void embn_kernel(const float* __restrict__ emb) {
    __shared__ float red[EMB];
    int e = blockIdx.x;
    int t = threadIdx.x;
    if (e == 0 && t == 0) g_nflag = 0;
    float v = emb[(size_t)t * E_EXP + e];
    red[t] = v * v;
    __syncthreads();
#pragma unroll
    for (int s = 128; s > 0; s >>= 1) {
        if (t < s) red[t] += red[t + s];
        __syncthreads();
    }
    float inv = 1.0f / sqrtf(red[0] + 1e-12f);
    g_embn[(size_t)t * E_EXP + e] = v * inv;
}

// ---------------------------------------------------------------------------
// mma.sync split-bf16 GEMM with fused in-kernel A split:
//   A: LDG fp32 x -> regs (1-iter prefetch) -> hi/lo bf16 -> STS swizzled
//   B: pre-split, cp.async 3-stage pipeline
// ---------------------------------------------------------------------------
#define NSTAGE      3
#define STAGE_BYTES 32768u
#define OFF_ALO     8192u
#define OFF_BHI     16384u
#define OFF_BLO     24576u
#define NKT         (D_DIM / 32)

__global__ void __launch_bounds__(256, 2) mma_gemm_kernel(
        const float* __restrict__ x, int M) {
    extern __shared__ __align__(128) unsigned char smem[];
    uint32_t sb = smem_u32(smem);
    int tid  = threadIdx.x;
    int lane = tid & 31;
    int w    = tid >> 5;
    int mw   = w & 3;
    int nw   = w >> 2;

    size_t bm = (size_t)blockIdx.y * 128;
    int    bn = blockIdx.x * 128;

    // loader: thread t covers row t/2, chunk pair (t&1)*2 + {0,1}
    int lr = tid >> 1;
    int lc = (tid & 1) * 2;
    const float* xrow = x + (bm + lr) * D_DIM + lc * 8;   // 16 floats per thread
    size_t brow = ((size_t)(bn + lr)) * (D_DIM * 2);

    float f[16];   // fp32 A prefetch buffer (one K-chunk: 16 floats)

    auto ldga = [&](int kt) {
        const float4* p = (const float4*)(xrow + (size_t)kt * 32);
#pragma unroll
        for (int q = 0; q < 4; q++) {
            float4 v = p[q];
            f[q * 4 + 0] = v.x; f[q * 4 + 1] = v.y;
            f[q * 4 + 2] = v.z; f[q * 4 + 3] = v.w;
        }
    };
    auto stsa = [&](int s) {
        uint32_t st = sb + (uint32_t)s * STAGE_BYTES;
#pragma unroll
        for (int c2 = 0; c2 < 2; c2++) {
            union { __nv_bfloat16 h[8]; uint4 v; } ph, pl;
#pragma unroll
            for (int i = 0; i < 8; i++) {
                float fv = f[c2 * 8 + i];
                __nv_bfloat16 hi = __float2bfloat16(fv);
                ph.h[i] = hi;
                pl.h[i] = __float2bfloat16(fv - __bfloat162float(hi));
            }
            uint32_t so = swz(lr, lc + c2);
            *(uint4*)(smem + (st - sb) + so) = ph.v;
            *(uint4*)(smem + (st - sb) + OFF_ALO + so) = pl.v;
        }
    };
    auto cpb = [&](int kt, int s) {
        uint32_t st = sb + (uint32_t)s * STAGE_BYTES;
        size_t gk = (size_t)kt * 64;
#pragma unroll
        for (int c = lc; c < lc + 2; c++) {
            uint32_t so = swz(lr, c);
            size_t go = gk + (size_t)c * 16;
            cp16(st + OFF_BHI + so, g_whi + brow + go);
            cp16(st + OFF_BLO + so, g_wlo + brow + go);
        }
        CP_COMMIT();
    };

    // prologue
    ldga(0); stsa(0); cpb(0, 0);
    ldga(1); stsa(1); cpb(1, 1);
    ldga(2);

    float acc[2][8][4];
#pragma unroll
    for (int i = 0; i < 2; i++)
#pragma unroll
        for (int j = 0; j < 8; j++)
#pragma unroll
            for (int q = 0; q < 4; q++) acc[i][j][q] = 0.0f;

    int a_r = (lane & 15);
    int a_cb = (lane >> 4);
    int b_r = (lane & 7) + ((lane >> 4) & 1) * 8;
    int b_cb = (lane >> 3) & 1;

    for (int kt = 0; kt < NKT; kt++) {
        CP_WAIT(1);
        __syncthreads();
        int nx = kt + 2;
        if (nx < NKT) {
            stsa(nx % NSTAGE);      // stage (kt+2)%3 == (kt-1)%3: free after sync
            cpb(nx, nx % NSTAGE);
            if (kt + 3 < NKT) ldga(kt + 3);
        }

        uint32_t st = sb + (uint32_t)(kt % NSTAGE) * STAGE_BYTES;

#pragma unroll
        for (int kh = 0; kh < 2; kh++) {
            uint32_t ahi[2][4], alo[2][4];
#pragma unroll
            for (int i = 0; i < 2; i++) {
                int r = mw * 32 + i * 16 + a_r;
                uint32_t ad = st + swz(r, 2 * kh + a_cb);
                LDSM4(ahi[i], ad);
                LDSM4(alo[i], ad + OFF_ALO);
            }
            uint32_t bhi[4][4], blo[4][4];
#pragma unroll
            for (int j2 = 0; j2 < 4; j2++) {
                int r = nw * 64 + j2 * 16 + b_r;
                uint32_t ad = st + OFF_BHI + swz(r, 2 * kh + b_cb);
                LDSM4(bhi[j2], ad);
                LDSM4(blo[j2], ad + 8192);
            }
#pragma unroll
            for (int i = 0; i < 2; i++) {
#pragma unroll
                for (int j = 0; j < 8; j++) {
                    uint32_t* bh = &bhi[j >> 1][(j & 1) * 2];
                    uint32_t* bl = &blo[j >> 1][(j & 1) * 2];
                    MMA16816(acc[i][j], ahi[i], bh[0], bh[1]);
                    MMA16816(acc[i][j], ahi[i], bl[0], bl[1]);
                    MMA16816(acc[i][j], alo[i], bh[0], bh[1]);
                }
            }
        }
        __syncthreads();   // all ldsm done before next iter's STS overwrites
    }

#pragma unroll
    for (int i = 0; i < 2; i++) {
#pragma unroll
        for (int j = 0; j < 8; j++) {
            size_t r0 = bm + mw * 32 + i * 16 + (lane >> 2);
            int col = bn + nw * 64 + j * 8 + 2 * (lane & 3);
            *(float2*)&g_proj[r0 * EMB + col] =
                make_float2(acc[i][j][0], acc[i][j][1]);
            *(float2*)&g_proj[(r0 + 8) * EMB + col] =
                make_float2(acc[i][j][2], acc[i][j][3]);
        }
    }
}

// ---------------------------------------------------------------------------
// Gate kernel: emits outputs + flags near-tie rows for exact refinement
// ---------------------------------------------------------------------------
__global__ void __launch_bounds__(256) gate_kernel(
        const float* __restrict__ tptr, float* __restrict__ out, int M) {
    extern __shared__ float sh[];
    float2* s_emb = (float2*)sh;
    int tid = threadIdx.x;
    int lane = tid & 31;
    int warp = tid >> 5;
    float* s_proj = sh + EMB * E_EXP + warp * EMB;

    for (int i = tid; i < EMB * 32; i += 256) {
        int k = i >> 5;
        int l = i & 31;
        s_emb[i] = make_float2(g_embn[k * 64 + l], g_embn[k * 64 + l + 32]);
    }
    __syncthreads();

    float temp = tptr[0];
    size_t nM = (size_t)M;
    float* out_ew  = out;
    float* out_ti  = out + nM * 64;
    float* out_lg  = out + nM * 66;
    float* out_cs  = out + nM * 130;
    float* out_raw = out + nM * 194;

    int gw = blockIdx.x * 8 + warp;
    int nw = gridDim.x * 8;

    for (int r = gw; r < M; r += nw) {
        const float4* pr = (const float4*)(g_proj + (size_t)r * EMB);
        float4 v0 = pr[lane];
        float4 v1 = pr[lane + 32];
        float ss = v0.x * v0.x + v0.y * v0.y + v0.z * v0.z + v0.w * v0.w
                 + v1.x * v1.x + v1.y * v1.y + v1.z * v1.z + v1.w * v1.w;
#pragma unroll
        for (int off = 16; off > 0; off >>= 1)
            ss += __shfl_xor_sync(0xffffffffu, ss, off);
        float inv = 1.0f / sqrtf(ss + 1e-12f);

        float4 n0 = make_float4(v0.x * inv, v0.y * inv, v0.z * inv, v0.w * inv);
        float4 n1 = make_float4(v1.x * inv, v1.y * inv, v1.z * inv, v1.w * inv);
        ((float4*)s_proj)[lane] = n0;
        ((float4*)s_proj)[lane + 32] = n1;
        __syncwarp();

        float c0 = 0.0f, c1 = 0.0f;
#pragma unroll 8
        for (int k = 0; k < EMB; k++) {
            float pn = s_proj[k];
            float2 e2 = s_emb[k * 32 + lane];
            c0 = fmaf(pn, e2.x, c0);
            c1 = fmaf(pn, e2.y, c1);
        }
        __syncwarp();

        float l0 = c0 * temp;
        float l1 = c1 * temp;

        float bv = l0; int bi = lane;
        if (l1 > bv) { bv = l1; bi = lane + 32; }
#pragma unroll
        for (int off = 16; off > 0; off >>= 1) {
            float ov = __shfl_xor_sync(0xffffffffu, bv, off);
            int   oi = __shfl_xor_sync(0xffffffffu, bi, off);
            if (ov > bv || (ov == bv && oi < bi)) { bv = ov; bi = oi; }
        }
        float t1v = bv; int t1i = bi;

        float m0 = (lane == t1i)      ? -INFINITY : l0;
        float m1 = (lane + 32 == t1i) ? -INFINITY : l1;
        bv = m0; bi = lane;
        if (m1 > bv || (m1 == bv && (lane + 32) < bi)) { bv = m1; bi = lane + 32; }
#pragma unroll
        for (int off = 16; off > 0; off >>= 1) {
            float ov = __shfl_xor_sync(0xffffffffu, bv, off);
            int   oi = __shfl_xor_sync(0xffffffffu, bi, off);
            if (ov > bv || (ov == bv && oi < bi)) { bv = ov; bi = oi; }
        }
        float t2v = bv; int t2i = bi;

        float p0 = (lane == t1i || lane == t2i) ? -INFINITY : l0;
        float p1 = (lane + 32 == t1i || lane + 32 == t2i) ? -INFINITY : l1;
        float t3v = fmaxf(p0, p1);
#pragma unroll
        for (int off = 16; off > 0; off >>= 1)
            t3v = fmaxf(t3v, __shfl_xor_sync(0xffffffffu, t3v, off));

        float ex0 = expf(l0 - t1v);
        float ex1 = expf(l1 - t1v);
        float tot = ex0 + ex1;
#pragma unroll
        for (int off = 16; off > 0; off >>= 1)
            tot += __shfl_xor_sync(0xffffffffu, tot, off);
        float r0 = ex0 / tot;
        float r1 = ex1 / tot;

        float eT = expf(t2v - t1v);
        float denom = 1.0f + eT;
        float w1 = 1.0f / denom;
        float w2 = eT / denom;
        float ew0 = (lane == t1i) ? w1 : ((lane == t2i) ? w2 : 0.0f);
        float ew1 = (lane + 32 == t1i) ? w1 : ((lane + 32 == t2i) ? w2 : 0.0f);

        size_t ro = (size_t)r * 64;
        out_ew[ro + lane]       = ew0;
        out_ew[ro + lane + 32]  = ew1;
        out_lg[ro + lane]       = l0;
        out_lg[ro + lane + 32]  = l1;
        out_cs[ro + lane]       = c0;
        out_cs[ro + lane + 32]  = c1;
        out_raw[ro + lane]      = r0;
        out_raw[ro + lane + 32] = r1;
        if (lane == 0) {
            out_ti[(size_t)r * 2]     = (float)t1i;
            out_ti[(size_t)r * 2 + 1] = (float)t2i;
            if ((t1v - t2v) < THETA || (t2v - t3v) < THETA) {
                int fi = atomicAdd(&g_nflag, 1);
                if (fi < MAXFLAG) g_flagrows[fi] = r;
            }
        }
    }
}

// ---------------------------------------------------------------------------
// Refinement: RB flagged rows per block — W read once, reused RB times.
// ---------------------------------------------------------------------------
__global__ void __launch_bounds__(256) refine_kernel(
        const float* __restrict__ x, const float* __restrict__ W,
        const float* __restrict__ tptr, float* __restrict__ out, int M) {
    extern __shared__ float rsh[];
    float* sx = rsh;                    // [RB][2048]
    float* sp = rsh + RB * D_DIM;       // [RB][256]

    int nf = g_nflag;
    if (nf > MAXFLAG) nf = MAXFLAG;
    int base = blockIdx.x * RB;
    if (base >= nf) return;
    int nr = nf - base;
    if (nr > RB) nr = RB;

    int t = threadIdx.x;
    int rows[RB];
#pragma unroll
    for (int lr = 0; lr < RB; lr++) {
        int fi = base + (lr < nr ? lr : nr - 1);
        rows[lr] = g_flagrows[fi];
    }
    for (int lr = 0; lr < RB; lr++)
        for (int i = t; i < D_DIM; i += 256)
            sx[lr * D_DIM + i] = x[(size_t)rows[lr] * D_DIM + i];
    __syncthreads();

    float acc[RB];
#pragma unroll
    for (int lr = 0; lr < RB; lr++) acc[lr] = 0.0f;
#pragma unroll 4
    for (int k = 0; k < D_DIM; k++) {
        float wv = W[(size_t)k * EMB + t];
#pragma unroll
        for (int lr = 0; lr < RB; lr++)
            acc[lr] = fmaf(sx[lr * D_DIM + k], wv, acc[lr]);
    }
#pragma unroll
    for (int lr = 0; lr < RB; lr++) sp[lr * EMB + t] = acc[lr];
    __syncthreads();

    int w = t >> 5, lane = t & 31;
    if (w < nr) {
        int r = rows[w];
        const float* rp = sp + w * EMB;

        float ss = 0.0f;
#pragma unroll
        for (int i = 0; i < 8; i++) {
            float v = rp[i * 32 + lane];
            ss = fmaf(v, v, ss);
        }
#pragma unroll
        for (int off = 16; off > 0; off >>= 1)
            ss += __shfl_xor_sync(0xffffffffu, ss, off);
        float inv = 1.0f / sqrtf(ss + 1e-12f);

        float c0 = 0.0f, c1 = 0.0f;
#pragma unroll 8
        for (int k = 0; k < EMB; k++) {
            float pn = rp[k] * inv;
            c0 = fmaf(pn, g_embn[k * E_EXP + lane], c0);
            c1 = fmaf(pn, g_embn[k * E_EXP + lane + 32], c1);
        }

        float temp = tptr[0];
        float l0 = c0 * temp;
        float l1 = c1 * temp;

        float bv = l0; int bi = lane;
        if (l1 > bv) { bv = l1; bi = lane + 32; }
#pragma unroll
        for (int off = 16; off > 0; off >>= 1) {
            float ov = __shfl_xor_sync(0xffffffffu, bv, off);
            int   oi = __shfl_xor_sync(0xffffffffu, bi, off);
            if (ov > bv || (ov == bv && oi < bi)) { bv = ov; bi = oi; }
        }
        float t1v = bv; int t1i = bi;

        float m0 = (lane == t1i)      ? -INFINITY : l0;
        float m1 = (lane + 32 == t1i) ? -INFINITY : l1;
        bv = m0; bi = lane;
        if (m1 > bv || (m1 == bv && (lane + 32) < bi)) { bv = m1; bi = lane + 32; }
#pragma unroll
        for (int off = 16; off > 0; off >>= 1) {
            float ov = __shfl_xor_sync(0xffffffffu, bv, off);
            int   oi = __shfl_xor_sync(0xffffffffu, bi, off);
            if (ov > bv || (ov == bv && oi < bi)) { bv = ov; bi = oi; }
        }
        float t2v = bv; int t2i = bi;

        float ex0 = expf(l0 - t1v);
        float ex1 = expf(l1 - t1v);
        float tot = ex0 + ex1;
#pragma unroll
        for (int off = 16; off > 0; off >>= 1)
            tot += __shfl_xor_sync(0xffffffffu, tot, off);
        float r0 = ex0 / tot;
        float r1 = ex1 / tot;

        float eT = expf(t2v - t1v);
        float denom = 1.0f + eT;
        float w1 = 1.0f / denom;
        float w2 = eT / denom;
        float ew0 = (lane == t1i) ? w1 : ((lane == t2i) ? w2 : 0.0f);
        float ew1 = (lane + 32 == t1i) ? w1 : ((lane + 32 == t2i) ? w2 : 0.0f);

        size_t nM = (size_t)M;
        size_t ro = (size_t)r * 64;
        out[ro + lane]              = ew0;
        out[ro + lane + 32]         = ew1;
        out[nM * 66 + ro + lane]    = l0;
        out[nM * 66 + ro + lane + 32]  = l1;
        out[nM * 130 + ro + lane]   = c0;
        out[nM * 130 + ro + lane + 32] = c1;
        out[nM * 194 + ro + lane]   = r0;
        out[nM * 194 + ro + lane + 32] = r1;
        if (lane == 0) {
            out[nM * 64 + (size_t)r * 2]     = (float)t1i;
            out[nM * 64 + (size_t)r * 2 + 1] = (float)t2i;
        }
    }
}

// ---------------------------------------------------------------------------
extern "C" void kernel_launch(void* const* d_in, const int* in_sizes, int n_in,
                              void* d_out, int out_size) {
    const float* x    = (const float*)d_in[0];
    const float* W    = (const float*)d_in[1];
    const float* emb  = (const float*)d_in[2];
    const float* temp = (const float*)d_in[3];
    float* out = (float*)d_out;

    int M = in_sizes[0] / D_DIM;

    splitw_kernel<<<256, 256>>>(W);
    embn_kernel<<<E_EXP, EMB>>>(emb);

    int gsmem = NSTAGE * (int)STAGE_BYTES;   // 98304 B
    cudaFuncSetAttribute(mma_gemm_kernel,
                         cudaFuncAttributeMaxDynamicSharedMemorySize, gsmem);
    dim3 grid(EMB / 128, M / 128);
    mma_gemm_kernel<<<grid, 256, gsmem>>>(x, M);

    int smem = (EMB * E_EXP + 8 * EMB) * (int)sizeof(float);
    cudaFuncSetAttribute(gate_kernel, cudaFuncAttributeMaxDynamicSharedMemorySize, smem);
    gate_kernel<<<444, 256, smem>>>(temp, out, M);

    int rsmem = (RB * D_DIM + RB * EMB) * (int)sizeof(float);  // 73728 B
    cudaFuncSetAttribute(refine_kernel,
                         cudaFuncAttributeMaxDynamicSharedMemorySize, rsmem);
    refine_kernel<<<(MAXFLAG + RB - 1) / RB, 256, rsmem>>>(x, W, temp, out, M);
}

// round 9
// speedup vs baseline: 1.4896x; 1.0827x over previous
#include <cuda_runtime.h>
#include <cuda_bf16.h>
#include <math.h>
#include <stdint.h>

#define D_DIM 2048
#define EMB   256
#define E_EXP 64
#define MAX_N 65536
#define THETA 2e-4f
#define MAXFLAG 8192
#define RB 8

// ---------------------------------------------------------------------------
// Device-global scratch
// ---------------------------------------------------------------------------
__device__ float g_proj[(size_t)MAX_N * EMB];
__device__ float g_embn[EMB * E_EXP];
__device__ int   g_nflag;
__device__ int   g_flagrows[MAXFLAG];

__device__ __align__(128) unsigned char g_whi[(size_t)EMB * D_DIM * 2];
__device__ __align__(128) unsigned char g_wlo[(size_t)EMB * D_DIM * 2];
// expert-major split emb_n^T, pre-swizzled ldmatrix layout: 8 chunks x 64 e x 64B
__device__ __align__(128) unsigned char g_ebhi[32768];
__device__ __align__(128) unsigned char g_eblo[32768];

// ---------------------------------------------------------------------------
// Base-ISA PTX helpers
// ---------------------------------------------------------------------------
__device__ __forceinline__ uint32_t smem_u32(const void* p) {
    uint32_t a;
    asm("{ .reg .u64 t; cvta.to.shared.u64 t, %1; cvt.u32.u64 %0, t; }"
        : "=r"(a) : "l"(p));
    return a;
}
__device__ __forceinline__ void cp16(uint32_t s, const void* g) {
    asm volatile("cp.async.cg.shared.global [%0], [%1], 16;"
                 :: "r"(s), "l"(g) : "memory");
}
#define CP_COMMIT() asm volatile("cp.async.commit_group;" ::: "memory")
#define CP_WAIT(n)  asm volatile("cp.async.wait_group %0;" :: "n"(n) : "memory")

#define LDSM4(R, a)                                                            \
    asm volatile("ldmatrix.sync.aligned.m8n8.x4.shared.b16 {%0,%1,%2,%3}, [%4];" \
        : "=r"((R)[0]), "=r"((R)[1]), "=r"((R)[2]), "=r"((R)[3]) : "r"(a))

#define MMA16816(C, A, B0, B1)                                                 \
    asm volatile(                                                              \
        "mma.sync.aligned.m16n8k16.row.col.f32.bf16.bf16.f32 "                 \
        "{%0,%1,%2,%3}, {%4,%5,%6,%7}, {%8,%9}, {%0,%1,%2,%3};"                \
        : "+f"((C)[0]), "+f"((C)[1]), "+f"((C)[2]), "+f"((C)[3])               \
        : "r"((A)[0]), "r"((A)[1]), "r"((A)[2]), "r"((A)[3]),                  \
          "r"(B0), "r"(B1))

__device__ __forceinline__ uint32_t swz(int r, int c) {
    return (uint32_t)(r * 64 + ((c ^ ((r >> 1) & 3)) * 16));
}

// ---------------------------------------------------------------------------
// split + transpose W [2048,256] -> [256][2048] (hi, lo) bf16
// ---------------------------------------------------------------------------
__global__ void __launch_bounds__(256) splitw_kernel(const float* __restrict__ W) {
    int idx = blockIdx.x * 256 + threadIdx.x;
    int n = idx >> 8;
    int k = (idx & 255) << 3;

    union { __nv_bfloat16 h[8]; uint4 v; } ph, pl;
#pragma unroll
    for (int i = 0; i < 8; i++) {
        float f = W[(size_t)(k + i) * EMB + n];
        __nv_bfloat16 hi = __float2bfloat16(f);
        ph.h[i] = hi;
        pl.h[i] = __float2bfloat16(f - __bfloat162float(hi));
    }
    size_t off = (size_t)n * (D_DIM * 2) + (size_t)k * 2;
    *(uint4*)(g_whi + off) = ph.v;
    *(uint4*)(g_wlo + off) = pl.v;
}

// ---------------------------------------------------------------------------
// normalize expert_emb columns; also emit expert-major split-bf16 emb_n^T
// in pre-swizzled ldmatrix layout. block e (64), thread k (256).
// ---------------------------------------------------------------------------
__global__ void embn_kernel(const float* __restrict__ emb) {
    __shared__ float red[EMB];
    int e = blockIdx.x;
    int k = threadIdx.x;
    if (e == 0 && k == 0) g_nflag = 0;
    float v = emb[(size_t)k * E_EXP + e];
    red[k] = v * v;
    __syncthreads();
#pragma unroll
    for (int s = 128; s > 0; s >>= 1) {
        if (k < s) red[k] += red[k + s];
        __syncthreads();
    }
    float inv = 1.0f / sqrtf(red[0] + 1e-12f);
    float vn = v * inv;
    g_embn[(size_t)k * E_EXP + e] = vn;

    __nv_bfloat16 hi = __float2bfloat16(vn);
    __nv_bfloat16 lo = __float2bfloat16(vn - __bfloat162float(hi));
    uint32_t addr = (uint32_t)(k >> 5) * 4096 + swz(e, (k & 31) >> 3) + (k & 7) * 2;
    *(__nv_bfloat16*)(g_ebhi + addr) = hi;
    *(__nv_bfloat16*)(g_eblo + addr) = lo;
}

// ---------------------------------------------------------------------------
// mma.sync split-bf16 GEMM with fused in-kernel A split (unchanged from R8)
// ---------------------------------------------------------------------------
#define NSTAGE      3
#define STAGE_BYTES 32768u
#define OFF_ALO     8192u
#define OFF_BHI     16384u
#define OFF_BLO     24576u
#define NKT         (D_DIM / 32)

__global__ void __launch_bounds__(256, 2) mma_gemm_kernel(
        const float* __restrict__ x, int M) {
    extern __shared__ __align__(128) unsigned char smem[];
    uint32_t sb = smem_u32(smem);
    int tid  = threadIdx.x;
    int lane = tid & 31;
    int w    = tid >> 5;
    int mw   = w & 3;
    int nw   = w >> 2;

    size_t bm = (size_t)blockIdx.y * 128;
    int    bn = blockIdx.x * 128;

    int lr = tid >> 1;
    int lc = (tid & 1) * 2;
    const float* xrow = x + (bm + lr) * D_DIM + lc * 8;
    size_t brow = ((size_t)(bn + lr)) * (D_DIM * 2);

    float f[16];

    auto ldga = [&](int kt) {
        const float4* p = (const float4*)(xrow + (size_t)kt * 32);
#pragma unroll
        for (int q = 0; q < 4; q++) {
            float4 v = p[q];
            f[q * 4 + 0] = v.x; f[q * 4 + 1] = v.y;
            f[q * 4 + 2] = v.z; f[q * 4 + 3] = v.w;
        }
    };
    auto stsa = [&](int s) {
        uint32_t st = (uint32_t)s * STAGE_BYTES;
#pragma unroll
        for (int c2 = 0; c2 < 2; c2++) {
            union { __nv_bfloat16 h[8]; uint4 v; } ph, pl;
#pragma unroll
            for (int i = 0; i < 8; i++) {
                float fv = f[c2 * 8 + i];
                __nv_bfloat16 hi = __float2bfloat16(fv);
                ph.h[i] = hi;
                pl.h[i] = __float2bfloat16(fv - __bfloat162float(hi));
            }
            uint32_t so = swz(lr, lc + c2);
            *(uint4*)(smem + st + so) = ph.v;
            *(uint4*)(smem + st + OFF_ALO + so) = pl.v;
        }
    };
    auto cpb = [&](int kt, int s) {
        uint32_t st = sb + (uint32_t)s * STAGE_BYTES;
        size_t gk = (size_t)kt * 64;
#pragma unroll
        for (int c = lc; c < lc + 2; c++) {
            uint32_t so = swz(lr, c);
            size_t go = gk + (size_t)c * 16;
            cp16(st + OFF_BHI + so, g_whi + brow + go);
            cp16(st + OFF_BLO + so, g_wlo + brow + go);
        }
        CP_COMMIT();
    };

    ldga(0); stsa(0); cpb(0, 0);
    ldga(1); stsa(1); cpb(1, 1);
    ldga(2);

    float acc[2][8][4];
#pragma unroll
    for (int i = 0; i < 2; i++)
#pragma unroll
        for (int j = 0; j < 8; j++)
#pragma unroll
            for (int q = 0; q < 4; q++) acc[i][j][q] = 0.0f;

    int a_r = (lane & 15);
    int a_cb = (lane >> 4);
    int b_r = (lane & 7) + ((lane >> 4) & 1) * 8;
    int b_cb = (lane >> 3) & 1;

    for (int kt = 0; kt < NKT; kt++) {
        CP_WAIT(1);
        __syncthreads();
        int nx = kt + 2;
        if (nx < NKT) {
            stsa(nx % NSTAGE);
            cpb(nx, nx % NSTAGE);
            if (kt + 3 < NKT) ldga(kt + 3);
        }

        uint32_t st = sb + (uint32_t)(kt % NSTAGE) * STAGE_BYTES;

#pragma unroll
        for (int kh = 0; kh < 2; kh++) {
            uint32_t ahi[2][4], alo[2][4];
#pragma unroll
            for (int i = 0; i < 2; i++) {
                int r = mw * 32 + i * 16 + a_r;
                uint32_t ad = st + swz(r, 2 * kh + a_cb);
                LDSM4(ahi[i], ad);
                LDSM4(alo[i], ad + OFF_ALO);
            }
            uint32_t bhi[4][4], blo[4][4];
#pragma unroll
            for (int j2 = 0; j2 < 4; j2++) {
                int r = nw * 64 + j2 * 16 + b_r;
                uint32_t ad = st + OFF_BHI + swz(r, 2 * kh + b_cb);
                LDSM4(bhi[j2], ad);
                LDSM4(blo[j2], ad + 8192);
            }
#pragma unroll
            for (int i = 0; i < 2; i++) {
#pragma unroll
                for (int j = 0; j < 8; j++) {
                    uint32_t* bh = &bhi[j >> 1][(j & 1) * 2];
                    uint32_t* bl = &blo[j >> 1][(j & 1) * 2];
                    MMA16816(acc[i][j], ahi[i], bh[0], bh[1]);
                    MMA16816(acc[i][j], ahi[i], bl[0], bl[1]);
                    MMA16816(acc[i][j], alo[i], bh[0], bh[1]);
                }
            }
        }
        __syncthreads();
    }

#pragma unroll
    for (int i = 0; i < 2; i++) {
#pragma unroll
        for (int j = 0; j < 8; j++) {
            size_t r0 = bm + mw * 32 + i * 16 + (lane >> 2);
            int col = bn + nw * 64 + j * 8 + 2 * (lane & 3);
            *(float2*)&g_proj[r0 * EMB + col] =
                make_float2(acc[i][j][0], acc[i][j][1]);
            *(float2*)&g_proj[(r0 + 8) * EMB + col] =
                make_float2(acc[i][j][2], acc[i][j][3]);
        }
    }
}

// ---------------------------------------------------------------------------
// Gate kernel v2: tensor-core cos. One CTA = 64 rows.
//  1. load proj[64][256] fp32, per-row sumsq, convert->split bf16 smem
//  2. mma 64x64x256 (3 products) against resident emb_n^T split
//  3. scale by inv norm -> smem cos; per-warp-row top2/softmax/flag/write
// ---------------------------------------------------------------------------
#define SM_BHI  0u
#define SM_BLO  32768u
#define SM_AHI  65536u
#define SM_ALO  98304u
#define SM_SCOS 131072u            // float[64][66]
#define SM_SSUM 147968u            // float[64]
#define GATE_SMEM 148224u

__global__ void __launch_bounds__(256) gate_kernel(
        const float* __restrict__ tptr, float* __restrict__ out, int M) {
    extern __shared__ __align__(128) unsigned char smem[];
    uint32_t sb = smem_u32(smem);
    float* scos = (float*)(smem + SM_SCOS);
    float* ssum = (float*)(smem + SM_SSUM);

    int t = threadIdx.x;
    int lane = t & 31;
    int w = t >> 5;

    // load resident B (emb_n^T split, pre-swizzled)
    {
        const uint4* shi = (const uint4*)g_ebhi;
        const uint4* slo = (const uint4*)g_eblo;
        uint4* dhi = (uint4*)(smem + SM_BHI);
        uint4* dlo = (uint4*)(smem + SM_BLO);
#pragma unroll
        for (int i = 0; i < 8; i++) {
            dhi[t + i * 256] = shi[t + i * 256];
            dlo[t + i * 256] = slo[t + i * 256];
        }
    }

    int gr0 = blockIdx.x * 64;
    int lr = t >> 2;          // row 0..63
    int q  = t & 3;           // k-quarter

    // load fp32 proj + sumsq + convert/STS
    float4 f[16];
    const float4* xp = (const float4*)(g_proj + (size_t)(gr0 + lr) * EMB + q * 64);
    float ss = 0.0f;
#pragma unroll
    for (int i = 0; i < 16; i++) {
        float4 v = xp[i];
        f[i] = v;
        ss += v.x * v.x + v.y * v.y + v.z * v.z + v.w * v.w;
    }
    ss += __shfl_xor_sync(0xffffffffu, ss, 1);
    ss += __shfl_xor_sync(0xffffffffu, ss, 2);
    if (q == 0) ssum[lr] = ss;

#pragma unroll
    for (int j = 0; j < 8; j++) {
        float fv[8] = {f[2*j].x, f[2*j].y, f[2*j].z, f[2*j].w,
                       f[2*j+1].x, f[2*j+1].y, f[2*j+1].z, f[2*j+1].w};
        union { __nv_bfloat16 h[8]; uint4 v; } ph, pl;
#pragma unroll
        for (int i = 0; i < 8; i++) {
            __nv_bfloat16 hi = __float2bfloat16(fv[i]);
            ph.h[i] = hi;
            pl.h[i] = __float2bfloat16(fv[i] - __bfloat162float(hi));
        }
        uint32_t so = (uint32_t)(q * 2 + (j >> 2)) * 4096 + swz(lr, j & 3);
        *(uint4*)(smem + SM_AHI + so) = ph.v;
        *(uint4*)(smem + SM_ALO + so) = pl.v;
    }
    __syncthreads();

    // mma: warp tile 16 rows x 32 experts. mw=w&3 rows, nw=w>>2 experts.
    int mw = w & 3;
    int nw = w >> 2;
    float acc[4][4];
#pragma unroll
    for (int j = 0; j < 4; j++)
#pragma unroll
        for (int qq = 0; qq < 4; qq++) acc[j][qq] = 0.0f;

    int a_r = lane & 15;
    int a_cb = lane >> 4;
    int b_r = (lane & 7) + ((lane >> 4) & 1) * 8;
    int b_cb = (lane >> 3) & 1;

#pragma unroll
    for (int kc = 0; kc < 8; kc++) {
#pragma unroll
        for (int kh = 0; kh < 2; kh++) {
            uint32_t ahi[4], alo[4], bhi[2][4], blo[2][4];
            uint32_t ca = SM_AHI + (uint32_t)kc * 4096 + swz(mw * 16 + a_r, 2 * kh + a_cb);
            LDSM4(ahi, sb + ca);
            LDSM4(alo, sb + ca + (SM_ALO - SM_AHI));
#pragma unroll
            for (int j2 = 0; j2 < 2; j2++) {
                uint32_t cb = SM_BHI + (uint32_t)kc * 4096
                            + swz(nw * 32 + j2 * 16 + b_r, 2 * kh + b_cb);
                LDSM4(bhi[j2], sb + cb);
                LDSM4(blo[j2], sb + cb + (SM_BLO - SM_BHI));
            }
#pragma unroll
            for (int j = 0; j < 4; j++) {
                uint32_t* bh = &bhi[j >> 1][(j & 1) * 2];
                uint32_t* bl = &blo[j >> 1][(j & 1) * 2];
                MMA16816(acc[j], ahi, bh[0], bh[1]);
                MMA16816(acc[j], ahi, bl[0], bl[1]);
                MMA16816(acc[j], alo, bh[0], bh[1]);
            }
        }
    }

    // scale by inv norm, store cos to smem
    int r0 = mw * 16 + (lane >> 2);
    float inv0 = 1.0f / sqrtf(ssum[r0] + 1e-12f);
    float inv1 = 1.0f / sqrtf(ssum[r0 + 8] + 1e-12f);
#pragma unroll
    for (int j = 0; j < 4; j++) {
        int col = nw * 32 + j * 8 + (lane & 3) * 2;
        scos[r0 * 66 + col]       = acc[j][0] * inv0;
        scos[r0 * 66 + col + 1]   = acc[j][1] * inv0;
        scos[(r0 + 8) * 66 + col]     = acc[j][2] * inv1;
        scos[(r0 + 8) * 66 + col + 1] = acc[j][3] * inv1;
    }
    __syncthreads();

    // gate math: warp w handles rows w*8 .. w*8+7
    float temp = tptr[0];
    size_t nM = (size_t)M;
    float* out_ew  = out;
    float* out_ti  = out + nM * 64;
    float* out_lg  = out + nM * 66;
    float* out_cs  = out + nM * 130;
    float* out_raw = out + nM * 194;

#pragma unroll
    for (int r8 = 0; r8 < 8; r8++) {
        int row = w * 8 + r8;
        int gr = gr0 + row;
        float c0 = scos[row * 66 + lane];
        float c1 = scos[row * 66 + lane + 32];
        float l0 = c0 * temp;
        float l1 = c1 * temp;

        float bv = l0; int bi = lane;
        if (l1 > bv) { bv = l1; bi = lane + 32; }
#pragma unroll
        for (int off = 16; off > 0; off >>= 1) {
            float ov = __shfl_xor_sync(0xffffffffu, bv, off);
            int   oi = __shfl_xor_sync(0xffffffffu, bi, off);
            if (ov > bv || (ov == bv && oi < bi)) { bv = ov; bi = oi; }
        }
        float t1v = bv; int t1i = bi;

        float m0 = (lane == t1i)      ? -INFINITY : l0;
        float m1 = (lane + 32 == t1i) ? -INFINITY : l1;
        bv = m0; bi = lane;
        if (m1 > bv || (m1 == bv && (lane + 32) < bi)) { bv = m1; bi = lane + 32; }
#pragma unroll
        for (int off = 16; off > 0; off >>= 1) {
            float ov = __shfl_xor_sync(0xffffffffu, bv, off);
            int   oi = __shfl_xor_sync(0xffffffffu, bi, off);
            if (ov > bv || (ov == bv && oi < bi)) { bv = ov; bi = oi; }
        }
        float t2v = bv; int t2i = bi;

        float p0 = (lane == t1i || lane == t2i) ? -INFINITY : l0;
        float p1 = (lane + 32 == t1i || lane + 32 == t2i) ? -INFINITY : l1;
        float t3v = fmaxf(p0, p1);
#pragma unroll
        for (int off = 16; off > 0; off >>= 1)
            t3v = fmaxf(t3v, __shfl_xor_sync(0xffffffffu, t3v, off));

        float ex0 = expf(l0 - t1v);
        float ex1 = expf(l1 - t1v);
        float tot = ex0 + ex1;
#pragma unroll
        for (int off = 16; off > 0; off >>= 1)
            tot += __shfl_xor_sync(0xffffffffu, tot, off);
        float r0s = ex0 / tot;
        float r1s = ex1 / tot;

        float eT = expf(t2v - t1v);
        float denom = 1.0f + eT;
        float w1 = 1.0f / denom;
        float w2 = eT / denom;
        float ew0 = (lane == t1i) ? w1 : ((lane == t2i) ? w2 : 0.0f);
        float ew1 = (lane + 32 == t1i) ? w1 : ((lane + 32 == t2i) ? w2 : 0.0f);

        size_t ro = (size_t)gr * 64;
        out_ew[ro + lane]       = ew0;
        out_ew[ro + lane + 32]  = ew1;
        out_lg[ro + lane]       = l0;
        out_lg[ro + lane + 32]  = l1;
        out_cs[ro + lane]       = c0;
        out_cs[ro + lane + 32]  = c1;
        out_raw[ro + lane]      = r0s;
        out_raw[ro + lane + 32] = r1s;
        if (lane == 0) {
            out_ti[(size_t)gr * 2]     = (float)t1i;
            out_ti[(size_t)gr * 2 + 1] = (float)t2i;
            if ((t1v - t2v) < THETA || (t2v - t3v) < THETA) {
                int fi = atomicAdd(&g_nflag, 1);
                if (fi < MAXFLAG) g_flagrows[fi] = gr;
            }
        }
    }
}

// ---------------------------------------------------------------------------
// Refinement (unchanged): RB flagged rows per block, exact fp32 recompute
// ---------------------------------------------------------------------------
__global__ void __launch_bounds__(256) refine_kernel(
        const float* __restrict__ x, const float* __restrict__ W,
        const float* __restrict__ tptr, float* __restrict__ out, int M) {
    extern __shared__ float rsh[];
    float* sx = rsh;
    float* sp = rsh + RB * D_DIM;

    int nf = g_nflag;
    if (nf > MAXFLAG) nf = MAXFLAG;
    int base = blockIdx.x * RB;
    if (base >= nf) return;
    int nr = nf - base;
    if (nr > RB) nr = RB;

    int t = threadIdx.x;
    int rows[RB];
#pragma unroll
    for (int lr = 0; lr < RB; lr++) {
        int fi = base + (lr < nr ? lr : nr - 1);
        rows[lr] = g_flagrows[fi];
    }
    for (int lr = 0; lr < RB; lr++)
        for (int i = t; i < D_DIM; i += 256)
            sx[lr * D_DIM + i] = x[(size_t)rows[lr] * D_DIM + i];
    __syncthreads();

    float acc[RB];
#pragma unroll
    for (int lr = 0; lr < RB; lr++) acc[lr] = 0.0f;
#pragma unroll 4
    for (int k = 0; k < D_DIM; k++) {
        float wv = W[(size_t)k * EMB + t];
#pragma unroll
        for (int lr = 0; lr < RB; lr++)
            acc[lr] = fmaf(sx[lr * D_DIM + k], wv, acc[lr]);
    }
#pragma unroll
    for (int lr = 0; lr < RB; lr++) sp[lr * EMB + t] = acc[lr];
    __syncthreads();

    int w = t >> 5, lane = t & 31;
    if (w < nr) {
        int r = rows[w];
        const float* rp = sp + w * EMB;

        float ss = 0.0f;
#pragma unroll
        for (int i = 0; i < 8; i++) {
            float v = rp[i * 32 + lane];
            ss = fmaf(v, v, ss);
        }
#pragma unroll
        for (int off = 16; off > 0; off >>= 1)
            ss += __shfl_xor_sync(0xffffffffu, ss, off);
        float inv = 1.0f / sqrtf(ss + 1e-12f);

        float c0 = 0.0f, c1 = 0.0f;
#pragma unroll 8
        for (int k = 0; k < EMB; k++) {
            float pn = rp[k] * inv;
            c0 = fmaf(pn, g_embn[k * E_EXP + lane], c0);
            c1 = fmaf(pn, g_embn[k * E_EXP + lane + 32], c1);
        }

        float temp = tptr[0];
        float l0 = c0 * temp;
        float l1 = c1 * temp;

        float bv = l0; int bi = lane;
        if (l1 > bv) { bv = l1; bi = lane + 32; }
#pragma unroll
        for (int off = 16; off > 0; off >>= 1) {
            float ov = __shfl_xor_sync(0xffffffffu, bv, off);
            int   oi = __shfl_xor_sync(0xffffffffu, bi, off);
            if (ov > bv || (ov == bv && oi < bi)) { bv = ov; bi = oi; }
        }
        float t1v = bv; int t1i = bi;

        float m0 = (lane == t1i)      ? -INFINITY : l0;
        float m1 = (lane + 32 == t1i) ? -INFINITY : l1;
        bv = m0; bi = lane;
        if (m1 > bv || (m1 == bv && (lane + 32) < bi)) { bv = m1; bi = lane + 32; }
#pragma unroll
        for (int off = 16; off > 0; off >>= 1) {
            float ov = __shfl_xor_sync(0xffffffffu, bv, off);
            int   oi = __shfl_xor_sync(0xffffffffu, bi, off);
            if (ov > bv || (ov == bv && oi < bi)) { bv = ov; bi = oi; }
        }
        float t2v = bv; int t2i = bi;

        float ex0 = expf(l0 - t1v);
        float ex1 = expf(l1 - t1v);
        float tot = ex0 + ex1;
#pragma unroll
        for (int off = 16; off > 0; off >>= 1)
            tot += __shfl_xor_sync(0xffffffffu, tot, off);
        float r0 = ex0 / tot;
        float r1 = ex1 / tot;

        float eT = expf(t2v - t1v);
        float denom = 1.0f + eT;
        float w1 = 1.0f / denom;
        float w2 = eT / denom;
        float ew0 = (lane == t1i) ? w1 : ((lane == t2i) ? w2 : 0.0f);
        float ew1 = (lane + 32 == t1i) ? w1 : ((lane + 32 == t2i) ? w2 : 0.0f);

        size_t nM = (size_t)M;
        size_t ro = (size_t)r * 64;
        out[ro + lane]              = ew0;
        out[ro + lane + 32]         = ew1;
        out[nM * 66 + ro + lane]    = l0;
        out[nM * 66 + ro + lane + 32]  = l1;
        out[nM * 130 + ro + lane]   = c0;
        out[nM * 130 + ro + lane + 32] = c1;
        out[nM * 194 + ro + lane]   = r0;
        out[nM * 194 + ro + lane + 32] = r1;
        if (lane == 0) {
            out[nM * 64 + (size_t)r * 2]     = (float)t1i;
            out[nM * 64 + (size_t)r * 2 + 1] = (float)t2i;
        }
    }
}

// ---------------------------------------------------------------------------
extern "C" void kernel_launch(void* const* d_in, const int* in_sizes, int n_in,
                              void* d_out, int out_size) {
    const float* x    = (const float*)d_in[0];
    const float* W    = (const float*)d_in[1];
    const float* emb  = (const float*)d_in[2];
    const float* temp = (const float*)d_in[3];
    float* out = (float*)d_out;

    int M = in_sizes[0] / D_DIM;

    splitw_kernel<<<256, 256>>>(W);
    embn_kernel<<<E_EXP, EMB>>>(emb);

    int gsmem = NSTAGE * (int)STAGE_BYTES;
    cudaFuncSetAttribute(mma_gemm_kernel,
                         cudaFuncAttributeMaxDynamicSharedMemorySize, gsmem);
    dim3 grid(EMB / 128, M / 128);
    mma_gemm_kernel<<<grid, 256, gsmem>>>(x, M);

    cudaFuncSetAttribute(gate_kernel,
                         cudaFuncAttributeMaxDynamicSharedMemorySize, (int)GATE_SMEM);
    gate_kernel<<<M / 64, 256, GATE_SMEM>>>(temp, out, M);

    int rsmem = (RB * D_DIM + RB * EMB) * (int)sizeof(float);
    cudaFuncSetAttribute(refine_kernel,
                         cudaFuncAttributeMaxDynamicSharedMemorySize, rsmem);
    refine_kernel<<<(MAXFLAG + RB - 1) / RB, 256, rsmem>>>(x, W, temp, out, M);
}

// round 10
// speedup vs baseline: 1.5649x; 1.0506x over previous
#include <cuda_runtime.h>
#include <cuda_bf16.h>
#include <math.h>
#include <stdint.h>

#define D_DIM 2048
#define EMB   256
#define E_EXP 64
#define MAX_N 65536
#define THETA 2e-4f
#define MAXFLAG 8192
#define RB 8

// ---------------------------------------------------------------------------
// Device-global scratch
// ---------------------------------------------------------------------------
__device__ float g_proj[(size_t)MAX_N * EMB];
__device__ float g_embn[EMB * E_EXP];
__device__ int   g_nflag;
__device__ int   g_flagrows[MAXFLAG];

__device__ __align__(128) unsigned char g_whi[(size_t)EMB * D_DIM * 2];
__device__ __align__(128) unsigned char g_wlo[(size_t)EMB * D_DIM * 2];
// expert-major split emb_n^T, pre-swizzled ldmatrix layout: 8 chunks x 64 e x 64B
__device__ __align__(128) unsigned char g_ebhi[32768];
__device__ __align__(128) unsigned char g_eblo[32768];

// ---------------------------------------------------------------------------
// Base-ISA PTX helpers
// ---------------------------------------------------------------------------
__device__ __forceinline__ uint32_t smem_u32(const void* p) {
    uint32_t a;
    asm("{ .reg .u64 t; cvta.to.shared.u64 t, %1; cvt.u32.u64 %0, t; }"
        : "=r"(a) : "l"(p));
    return a;
}
__device__ __forceinline__ void cp16(uint32_t s, const void* g) {
    asm volatile("cp.async.cg.shared.global [%0], [%1], 16;"
                 :: "r"(s), "l"(g) : "memory");
}
#define CP_COMMIT() asm volatile("cp.async.commit_group;" ::: "memory")
#define CP_WAIT(n)  asm volatile("cp.async.wait_group %0;" :: "n"(n) : "memory")

#define LDSM4(R, a)                                                            \
    asm volatile("ldmatrix.sync.aligned.m8n8.x4.shared.b16 {%0,%1,%2,%3}, [%4];" \
        : "=r"((R)[0]), "=r"((R)[1]), "=r"((R)[2]), "=r"((R)[3]) : "r"(a))

#define MMA16816(C, A, B0, B1)                                                 \
    asm volatile(                                                              \
        "mma.sync.aligned.m16n8k16.row.col.f32.bf16.bf16.f32 "                 \
        "{%0,%1,%2,%3}, {%4,%5,%6,%7}, {%8,%9}, {%0,%1,%2,%3};"                \
        : "+f"((C)[0]), "+f"((C)[1]), "+f"((C)[2]), "+f"((C)[3])               \
        : "r"((A)[0]), "r"((A)[1]), "r"((A)[2]), "r"((A)[3]),                  \
          "r"(B0), "r"(B1))

__device__ __forceinline__ uint32_t swz(int r, int c) {
    return (uint32_t)(r * 64 + ((c ^ ((r >> 1) & 3)) * 16));
}

// ---------------------------------------------------------------------------
// split + transpose W [2048,256] -> [256][2048] (hi, lo) bf16
// ---------------------------------------------------------------------------
__global__ void __launch_bounds__(256) splitw_kernel(const float* __restrict__ W) {
    int idx = blockIdx.x * 256 + threadIdx.x;
    int n = idx >> 8;
    int k = (idx & 255) << 3;

    union { __nv_bfloat16 h[8]; uint4 v; } ph, pl;
#pragma unroll
    for (int i = 0; i < 8; i++) {
        float f = W[(size_t)(k + i) * EMB + n];
        __nv_bfloat16 hi = __float2bfloat16(f);
        ph.h[i] = hi;
        pl.h[i] = __float2bfloat16(f - __bfloat162float(hi));
    }
    size_t off = (size_t)n * (D_DIM * 2) + (size_t)k * 2;
    *(uint4*)(g_whi + off) = ph.v;
    *(uint4*)(g_wlo + off) = pl.v;
}

// ---------------------------------------------------------------------------
// normalize expert_emb columns; emit expert-major split emb_n^T (swizzled)
// ---------------------------------------------------------------------------
__global__ void embn_kernel(const float* __restrict__ emb) {
    __shared__ float red[EMB];
    int e = blockIdx.x;
    int k = threadIdx.x;
    if (e == 0 && k == 0) g_nflag = 0;
    float v = emb[(size_t)k * E_EXP + e];
    red[k] = v * v;
    __syncthreads();
#pragma unroll
    for (int s = 128; s > 0; s >>= 1) {
        if (k < s) red[k] += red[k + s];
        __syncthreads();
    }
    float inv = 1.0f / sqrtf(red[0] + 1e-12f);
    float vn = v * inv;
    g_embn[(size_t)k * E_EXP + e] = vn;

    __nv_bfloat16 hi = __float2bfloat16(vn);
    __nv_bfloat16 lo = __float2bfloat16(vn - __bfloat162float(hi));
    uint32_t addr = (uint32_t)(k >> 5) * 4096 + swz(e, (k & 31) >> 3) + (k & 7) * 2;
    *(__nv_bfloat16*)(g_ebhi + addr) = hi;
    *(__nv_bfloat16*)(g_eblo + addr) = lo;
}

// ---------------------------------------------------------------------------
// GEMM v3: 512 threads, 16 warps, warp tile 32x32, 4-stage pipeline,
// single barrier/iter, fused in-kernel A split (no spills: ~100 regs).
// ---------------------------------------------------------------------------
#define NSTAGE      4
#define STAGE_BYTES 32768u
#define OFF_ALO     8192u
#define OFF_BHI     16384u
#define OFF_BLO     24576u
#define NKT         (D_DIM / 32)   // 64

__global__ void __launch_bounds__(512, 1) mma_gemm_kernel(
        const float* __restrict__ x, int M) {
    extern __shared__ __align__(128) unsigned char smem[];
    uint32_t sb = smem_u32(smem);
    int tid  = threadIdx.x;
    int lane = tid & 31;
    int w    = tid >> 5;     // 0..15
    int mw   = w & 3;        // M slice (32 rows)
    int nw   = w >> 2;       // N slice (32 cols)

    size_t bm = (size_t)blockIdx.y * 128;
    int    bn = blockIdx.x * 128;

    // loaders: thread t -> row t/4 (0..127), 16B chunk t&3
    int lr = tid >> 2;
    int lq = tid & 3;
    const float* xrow = x + (bm + lr) * D_DIM + lq * 8;
    size_t brow = (size_t)(bn + lr) * (D_DIM * 2) + (size_t)lq * 16;

    float f[8];
    auto ldga = [&](int kt) {
        const float4* p = (const float4*)(xrow + (size_t)kt * 32);
        float4 v0 = p[0], v1 = p[1];
        f[0] = v0.x; f[1] = v0.y; f[2] = v0.z; f[3] = v0.w;
        f[4] = v1.x; f[5] = v1.y; f[6] = v1.z; f[7] = v1.w;
    };
    auto stsa = [&](int s) {
        union { __nv_bfloat16 h[8]; uint4 v; } ph, pl;
#pragma unroll
        for (int i = 0; i < 8; i++) {
            __nv_bfloat16 hi = __float2bfloat16(f[i]);
            ph.h[i] = hi;
            pl.h[i] = __float2bfloat16(f[i] - __bfloat162float(hi));
        }
        uint32_t so = (uint32_t)s * STAGE_BYTES + swz(lr, lq);
        *(uint4*)(smem + so) = ph.v;
        *(uint4*)(smem + so + OFF_ALO) = pl.v;
    };
    auto cpb = [&](int kt, int s) {
        uint32_t st = sb + (uint32_t)s * STAGE_BYTES + swz(lr, lq);
        size_t go = brow + (size_t)kt * 64;
        cp16(st + OFF_BHI, g_whi + go);
        cp16(st + OFF_BLO, g_wlo + go);
        CP_COMMIT();
    };

    // prologue: stages 0..2 (groups 0,1,2 = chunks 0,1,2)
#pragma unroll
    for (int p = 0; p < 3; p++) { ldga(p); stsa(p); cpb(p, p); }

    float acc[2][4][4];
#pragma unroll
    for (int i = 0; i < 2; i++)
#pragma unroll
        for (int j = 0; j < 4; j++)
#pragma unroll
            for (int q = 0; q < 4; q++) acc[i][j][q] = 0.0f;

    int a_r  = lane & 15;
    int a_cb = lane >> 4;
    int b_r  = (lane & 7) + ((lane >> 4) & 1) * 8;
    int b_cb = (lane >> 3) & 1;

    for (int kt = 0; kt < NKT; kt++) {
        CP_WAIT(2);
        __syncthreads();

        int nx = kt + 3;
        bool pf = nx < NKT;
        if (pf) { ldga(nx); cpb(nx, nx & 3); }
        else    { CP_COMMIT(); }            // keep wait_group accounting exact

        uint32_t st = sb + (uint32_t)(kt & 3) * STAGE_BYTES;

#pragma unroll
        for (int kh = 0; kh < 2; kh++) {
            uint32_t ahi[2][4], alo[2][4];
#pragma unroll
            for (int i = 0; i < 2; i++) {
                int r = mw * 32 + i * 16 + a_r;
                uint32_t ad = st + swz(r, 2 * kh + a_cb);
                LDSM4(ahi[i], ad);
                LDSM4(alo[i], ad + OFF_ALO);
            }
            uint32_t bhi[2][4], blo[2][4];
#pragma unroll
            for (int j2 = 0; j2 < 2; j2++) {
                int r = nw * 32 + j2 * 16 + b_r;
                uint32_t ad = st + OFF_BHI + swz(r, 2 * kh + b_cb);
                LDSM4(bhi[j2], ad);
                LDSM4(blo[j2], ad + 8192);
            }
#pragma unroll
            for (int i = 0; i < 2; i++) {
#pragma unroll
                for (int j = 0; j < 4; j++) {
                    uint32_t* bh = &bhi[j >> 1][(j & 1) * 2];
                    uint32_t* bl = &blo[j >> 1][(j & 1) * 2];
                    MMA16816(acc[i][j], ahi[i], bh[0], bh[1]);
                    MMA16816(acc[i][j], ahi[i], bl[0], bl[1]);
                    MMA16816(acc[i][j], alo[i], bh[0], bh[1]);
                }
            }
        }
        if (pf) stsa(nx & 3);   // stage (kt-1)&3: all its ldsm done (top sync)
    }

#pragma unroll
    for (int i = 0; i < 2; i++) {
#pragma unroll
        for (int j = 0; j < 4; j++) {
            size_t r0 = bm + mw * 32 + i * 16 + (lane >> 2);
            int col = bn + nw * 32 + j * 8 + 2 * (lane & 3);
            *(float2*)&g_proj[r0 * EMB + col] =
                make_float2(acc[i][j][0], acc[i][j][1]);
            *(float2*)&g_proj[(r0 + 8) * EMB + col] =
                make_float2(acc[i][j][2], acc[i][j][3]);
        }
    }
}

// ---------------------------------------------------------------------------
// Gate kernel v2 (unchanged from R9): tensor-core cos, one CTA = 64 rows
// ---------------------------------------------------------------------------
#define SM_BHI  0u
#define SM_BLO  32768u
#define SM_AHI  65536u
#define SM_ALO  98304u
#define SM_SCOS 131072u            // float[64][66]
#define SM_SSUM 147968u            // float[64]
#define GATE_SMEM 148224u

__global__ void __launch_bounds__(256) gate_kernel(
        const float* __restrict__ tptr, float* __restrict__ out, int M) {
    extern __shared__ __align__(128) unsigned char smem[];
    uint32_t sb = smem_u32(smem);
    float* scos = (float*)(smem + SM_SCOS);
    float* ssum = (float*)(smem + SM_SSUM);

    int t = threadIdx.x;
    int lane = t & 31;
    int w = t >> 5;

    {
        const uint4* shi = (const uint4*)g_ebhi;
        const uint4* slo = (const uint4*)g_eblo;
        uint4* dhi = (uint4*)(smem + SM_BHI);
        uint4* dlo = (uint4*)(smem + SM_BLO);
#pragma unroll
        for (int i = 0; i < 8; i++) {
            dhi[t + i * 256] = shi[t + i * 256];
            dlo[t + i * 256] = slo[t + i * 256];
        }
    }

    int gr0 = blockIdx.x * 64;
    int lr = t >> 2;
    int q  = t & 3;

    float4 f[16];
    const float4* xp = (const float4*)(g_proj + (size_t)(gr0 + lr) * EMB + q * 64);
    float ss = 0.0f;
#pragma unroll
    for (int i = 0; i < 16; i++) {
        float4 v = xp[i];
        f[i] = v;
        ss += v.x * v.x + v.y * v.y + v.z * v.z + v.w * v.w;
    }
    ss += __shfl_xor_sync(0xffffffffu, ss, 1);
    ss += __shfl_xor_sync(0xffffffffu, ss, 2);
    if (q == 0) ssum[lr] = ss;

#pragma unroll
    for (int j = 0; j < 8; j++) {
        float fv[8] = {f[2*j].x, f[2*j].y, f[2*j].z, f[2*j].w,
                       f[2*j+1].x, f[2*j+1].y, f[2*j+1].z, f[2*j+1].w};
        union { __nv_bfloat16 h[8]; uint4 v; } ph, pl;
#pragma unroll
        for (int i = 0; i < 8; i++) {
            __nv_bfloat16 hi = __float2bfloat16(fv[i]);
            ph.h[i] = hi;
            pl.h[i] = __float2bfloat16(fv[i] - __bfloat162float(hi));
        }
        uint32_t so = (uint32_t)(q * 2 + (j >> 2)) * 4096 + swz(lr, j & 3);
        *(uint4*)(smem + SM_AHI + so) = ph.v;
        *(uint4*)(smem + SM_ALO + so) = pl.v;
    }
    __syncthreads();

    int mw = w & 3;
    int nw = w >> 2;
    float acc[4][4];
#pragma unroll
    for (int j = 0; j < 4; j++)
#pragma unroll
        for (int qq = 0; qq < 4; qq++) acc[j][qq] = 0.0f;

    int a_r = lane & 15;
    int a_cb = lane >> 4;
    int b_r = (lane & 7) + ((lane >> 4) & 1) * 8;
    int b_cb = (lane >> 3) & 1;

#pragma unroll
    for (int kc = 0; kc < 8; kc++) {
#pragma unroll
        for (int kh = 0; kh < 2; kh++) {
            uint32_t ahi[4], alo[4], bhi[2][4], blo[2][4];
            uint32_t ca = SM_AHI + (uint32_t)kc * 4096 + swz(mw * 16 + a_r, 2 * kh + a_cb);
            LDSM4(ahi, sb + ca);
            LDSM4(alo, sb + ca + (SM_ALO - SM_AHI));
#pragma unroll
            for (int j2 = 0; j2 < 2; j2++) {
                uint32_t cb = SM_BHI + (uint32_t)kc * 4096
                            + swz(nw * 32 + j2 * 16 + b_r, 2 * kh + b_cb);
                LDSM4(bhi[j2], sb + cb);
                LDSM4(blo[j2], sb + cb + (SM_BLO - SM_BHI));
            }
#pragma unroll
            for (int j = 0; j < 4; j++) {
                uint32_t* bh = &bhi[j >> 1][(j & 1) * 2];
                uint32_t* bl = &blo[j >> 1][(j & 1) * 2];
                MMA16816(acc[j], ahi, bh[0], bh[1]);
                MMA16816(acc[j], ahi, bl[0], bl[1]);
                MMA16816(acc[j], alo, bh[0], bh[1]);
            }
        }
    }

    int r0 = mw * 16 + (lane >> 2);
    float inv0 = 1.0f / sqrtf(ssum[r0] + 1e-12f);
    float inv1 = 1.0f / sqrtf(ssum[r0 + 8] + 1e-12f);
#pragma unroll
    for (int j = 0; j < 4; j++) {
        int col = nw * 32 + j * 8 + (lane & 3) * 2;
        scos[r0 * 66 + col]       = acc[j][0] * inv0;
        scos[r0 * 66 + col + 1]   = acc[j][1] * inv0;
        scos[(r0 + 8) * 66 + col]     = acc[j][2] * inv1;
        scos[(r0 + 8) * 66 + col + 1] = acc[j][3] * inv1;
    }
    __syncthreads();

    float temp = tptr[0];
    size_t nM = (size_t)M;
    float* out_ew  = out;
    float* out_ti  = out + nM * 64;
    float* out_lg  = out + nM * 66;
    float* out_cs  = out + nM * 130;
    float* out_raw = out + nM * 194;

#pragma unroll
    for (int r8 = 0; r8 < 8; r8++) {
        int row = w * 8 + r8;
        int gr = gr0 + row;
        float c0 = scos[row * 66 + lane];
        float c1 = scos[row * 66 + lane + 32];
        float l0 = c0 * temp;
        float l1 = c1 * temp;

        float bv = l0; int bi = lane;
        if (l1 > bv) { bv = l1; bi = lane + 32; }
#pragma unroll
        for (int off = 16; off > 0; off >>= 1) {
            float ov = __shfl_xor_sync(0xffffffffu, bv, off);
            int   oi = __shfl_xor_sync(0xffffffffu, bi, off);
            if (ov > bv || (ov == bv && oi < bi)) { bv = ov; bi = oi; }
        }
        float t1v = bv; int t1i = bi;

        float m0 = (lane == t1i)      ? -INFINITY : l0;
        float m1 = (lane + 32 == t1i) ? -INFINITY : l1;
        bv = m0; bi = lane;
        if (m1 > bv || (m1 == bv && (lane + 32) < bi)) { bv = m1; bi = lane + 32; }
#pragma unroll
        for (int off = 16; off > 0; off >>= 1) {
            float ov = __shfl_xor_sync(0xffffffffu, bv, off);
            int   oi = __shfl_xor_sync(0xffffffffu, bi, off);
            if (ov > bv || (ov == bv && oi < bi)) { bv = ov; bi = oi; }
        }
        float t2v = bv; int t2i = bi;

        float p0 = (lane == t1i || lane == t2i) ? -INFINITY : l0;
        float p1 = (lane + 32 == t1i || lane + 32 == t2i) ? -INFINITY : l1;
        float t3v = fmaxf(p0, p1);
#pragma unroll
        for (int off = 16; off > 0; off >>= 1)
            t3v = fmaxf(t3v, __shfl_xor_sync(0xffffffffu, t3v, off));

        float ex0 = expf(l0 - t1v);
        float ex1 = expf(l1 - t1v);
        float tot = ex0 + ex1;
#pragma unroll
        for (int off = 16; off > 0; off >>= 1)
            tot += __shfl_xor_sync(0xffffffffu, tot, off);
        float r0s = ex0 / tot;
        float r1s = ex1 / tot;

        float eT = expf(t2v - t1v);
        float denom = 1.0f + eT;
        float w1 = 1.0f / denom;
        float w2 = eT / denom;
        float ew0 = (lane == t1i) ? w1 : ((lane == t2i) ? w2 : 0.0f);
        float ew1 = (lane + 32 == t1i) ? w1 : ((lane + 32 == t2i) ? w2 : 0.0f);

        size_t ro = (size_t)gr * 64;
        out_ew[ro + lane]       = ew0;
        out_ew[ro + lane + 32]  = ew1;
        out_lg[ro + lane]       = l0;
        out_lg[ro + lane + 32]  = l1;
        out_cs[ro + lane]       = c0;
        out_cs[ro + lane + 32]  = c1;
        out_raw[ro + lane]      = r0s;
        out_raw[ro + lane + 32] = r1s;
        if (lane == 0) {
            out_ti[(size_t)gr * 2]     = (float)t1i;
            out_ti[(size_t)gr * 2 + 1] = (float)t2i;
            if ((t1v - t2v) < THETA || (t2v - t3v) < THETA) {
                int fi = atomicAdd(&g_nflag, 1);
                if (fi < MAXFLAG) g_flagrows[fi] = gr;
            }
        }
    }
}

// ---------------------------------------------------------------------------
// Refinement (unchanged): RB flagged rows per block, exact fp32 recompute
// ---------------------------------------------------------------------------
__global__ void __launch_bounds__(256) refine_kernel(
        const float* __restrict__ x, const float* __restrict__ W,
        const float* __restrict__ tptr, float* __restrict__ out, int M) {
    extern __shared__ float rsh[];
    float* sx = rsh;
    float* sp = rsh + RB * D_DIM;

    int nf = g_nflag;
    if (nf > MAXFLAG) nf = MAXFLAG;
    int base = blockIdx.x * RB;
    if (base >= nf) return;
    int nr = nf - base;
    if (nr > RB) nr = RB;

    int t = threadIdx.x;
    int rows[RB];
#pragma unroll
    for (int lr = 0; lr < RB; lr++) {
        int fi = base + (lr < nr ? lr : nr - 1);
        rows[lr] = g_flagrows[fi];
    }
    for (int lr = 0; lr < RB; lr++)
        for (int i = t; i < D_DIM; i += 256)
            sx[lr * D_DIM + i] = x[(size_t)rows[lr] * D_DIM + i];
    __syncthreads();

    float acc[RB];
#pragma unroll
    for (int lr = 0; lr < RB; lr++) acc[lr] = 0.0f;
#pragma unroll 4
    for (int k = 0; k < D_DIM; k++) {
        float wv = W[(size_t)k * EMB + t];
#pragma unroll
        for (int lr = 0; lr < RB; lr++)
            acc[lr] = fmaf(sx[lr * D_DIM + k], wv, acc[lr]);
    }
#pragma unroll
    for (int lr = 0; lr < RB; lr++) sp[lr * EMB + t] = acc[lr];
    __syncthreads();

    int w = t >> 5, lane = t & 31;
    if (w < nr) {
        int r = rows[w];
        const float* rp = sp + w * EMB;

        float ss = 0.0f;
#pragma unroll
        for (int i = 0; i < 8; i++) {
            float v = rp[i * 32 + lane];
            ss = fmaf(v, v, ss);
        }
#pragma unroll
        for (int off = 16; off > 0; off >>= 1)
            ss += __shfl_xor_sync(0xffffffffu, ss, off);
        float inv = 1.0f / sqrtf(ss + 1e-12f);

        float c0 = 0.0f, c1 = 0.0f;
#pragma unroll 8
        for (int k = 0; k < EMB; k++) {
            float pn = rp[k] * inv;
            c0 = fmaf(pn, g_embn[k * E_EXP + lane], c0);
            c1 = fmaf(pn, g_embn[k * E_EXP + lane + 32], c1);
        }

        float temp = tptr[0];
        float l0 = c0 * temp;
        float l1 = c1 * temp;

        float bv = l0; int bi = lane;
        if (l1 > bv) { bv = l1; bi = lane + 32; }
#pragma unroll
        for (int off = 16; off > 0; off >>= 1) {
            float ov = __shfl_xor_sync(0xffffffffu, bv, off);
            int   oi = __shfl_xor_sync(0xffffffffu, bi, off);
            if (ov > bv || (ov == bv && oi < bi)) { bv = ov; bi = oi; }
        }
        float t1v = bv; int t1i = bi;

        float m0 = (lane == t1i)      ? -INFINITY : l0;
        float m1 = (lane + 32 == t1i) ? -INFINITY : l1;
        bv = m0; bi = lane;
        if (m1 > bv || (m1 == bv && (lane + 32) < bi)) { bv = m1; bi = lane + 32; }
#pragma unroll
        for (int off = 16; off > 0; off >>= 1) {
            float ov = __shfl_xor_sync(0xffffffffu, bv, off);
            int   oi = __shfl_xor_sync(0xffffffffu, bi, off);
            if (ov > bv || (ov == bv && oi < bi)) { bv = ov; bi = oi; }
        }
        float t2v = bv; int t2i = bi;

        float ex0 = expf(l0 - t1v);
        float ex1 = expf(l1 - t1v);
        float tot = ex0 + ex1;
#pragma unroll
        for (int off = 16; off > 0; off >>= 1)
            tot += __shfl_xor_sync(0xffffffffu, tot, off);
        float r0 = ex0 / tot;
        float r1 = ex1 / tot;

        float eT = expf(t2v - t1v);
        float denom = 1.0f + eT;
        float w1 = 1.0f / denom;
        float w2 = eT / denom;
        float ew0 = (lane == t1i) ? w1 : ((lane == t2i) ? w2 : 0.0f);
        float ew1 = (lane + 32 == t1i) ? w1 : ((lane + 32 == t2i) ? w2 : 0.0f);

        size_t nM = (size_t)M;
        size_t ro = (size_t)r * 64;
        out[ro + lane]              = ew0;
        out[ro + lane + 32]         = ew1;
        out[nM * 66 + ro + lane]    = l0;
        out[nM * 66 + ro + lane + 32]  = l1;
        out[nM * 130 + ro + lane]   = c0;
        out[nM * 130 + ro + lane + 32] = c1;
        out[nM * 194 + ro + lane]   = r0;
        out[nM * 194 + ro + lane + 32] = r1;
        if (lane == 0) {
            out[nM * 64 + (size_t)r * 2]     = (float)t1i;
            out[nM * 64 + (size_t)r * 2 + 1] = (float)t2i;
        }
    }
}

// ---------------------------------------------------------------------------
extern "C" void kernel_launch(void* const* d_in, const int* in_sizes, int n_in,
                              void* d_out, int out_size) {
    const float* x    = (const float*)d_in[0];
    const float* W    = (const float*)d_in[1];
    const float* emb  = (const float*)d_in[2];
    const float* temp = (const float*)d_in[3];
    float* out = (float*)d_out;

    int M = in_sizes[0] / D_DIM;

    splitw_kernel<<<256, 256>>>(W);
    embn_kernel<<<E_EXP, EMB>>>(emb);

    int gsmem = NSTAGE * (int)STAGE_BYTES;   // 131072 B
    cudaFuncSetAttribute(mma_gemm_kernel,
                         cudaFuncAttributeMaxDynamicSharedMemorySize, gsmem);
    dim3 grid(EMB / 128, M / 128);
    mma_gemm_kernel<<<grid, 512, gsmem>>>(x, M);

    cudaFuncSetAttribute(gate_kernel,
                         cudaFuncAttributeMaxDynamicSharedMemorySize, (int)GATE_SMEM);
    gate_kernel<<<M / 64, 256, GATE_SMEM>>>(temp, out, M);

    int rsmem = (RB * D_DIM + RB * EMB) * (int)sizeof(float);
    cudaFuncSetAttribute(refine_kernel,
                         cudaFuncAttributeMaxDynamicSharedMemorySize, rsmem);
    refine_kernel<<<(MAXFLAG + RB - 1) / RB, 256, rsmem>>>(x, W, temp, out, M);
}